// round 1
// baseline (speedup 1.0000x reference)
#include <cuda_runtime.h>
#include <cuda_bf16.h>
#include <math.h>

#define BATCH 2
#define SEQ   2048
#define DMODEL 768
#define NHEAD 12
#define HDIM  64
#define M_ROWS (BATCH * SEQ)          // 4096
#define QKV_COLS (NHEAD * 3 * HDIM)   // 2304

__device__ float g_q [BATCH * NHEAD * SEQ * HDIM];
__device__ float g_k [BATCH * NHEAD * SEQ * HDIM];
__device__ float g_v [BATCH * NHEAD * SEQ * HDIM];
__device__ float g_sa[M_ROWS * DMODEL];

// ---------------------------------------------------------------------------
// GEMM 1: QKV projection.  out[m,c] = sum_d X[m,d]*W[c,d] + bias[c]
// Epilogue scatters into g_k/g_q/g_v ([B,H,N,HD]); q scaled by 1/sqrt(HD).
// ---------------------------------------------------------------------------
__global__ __launch_bounds__(256)
void gemm_qkv_kernel(const float* __restrict__ X,
                     const float* __restrict__ W,
                     const float* __restrict__ bias)
{
    __shared__ float As[16][68];
    __shared__ float Bs[16][68];

    const int tx = threadIdx.x % 16;
    const int ty = threadIdx.x / 16;
    const int m0 = blockIdx.y * 64;
    const int n0 = blockIdx.x * 64;

    float acc[4][4];
#pragma unroll
    for (int i = 0; i < 4; i++)
#pragma unroll
        for (int j = 0; j < 4; j++) acc[i][j] = 0.f;

    for (int k0 = 0; k0 < DMODEL; k0 += 16) {
        {
            const int t   = threadIdx.x;
            const int row = t >> 2;
            const int kq  = (t & 3) * 4;
            float4 a = *(const float4*)&X[(size_t)(m0 + row) * DMODEL + k0 + kq];
            As[kq + 0][row] = a.x; As[kq + 1][row] = a.y;
            As[kq + 2][row] = a.z; As[kq + 3][row] = a.w;
            float4 b = *(const float4*)&W[(size_t)(n0 + row) * DMODEL + k0 + kq];
            Bs[kq + 0][row] = b.x; Bs[kq + 1][row] = b.y;
            Bs[kq + 2][row] = b.z; Bs[kq + 3][row] = b.w;
        }
        __syncthreads();

#pragma unroll
        for (int k = 0; k < 16; k++) {
            float4 a4 = *(const float4*)&As[k][ty * 4];
            float4 b4 = *(const float4*)&Bs[k][tx * 4];
            float a[4] = {a4.x, a4.y, a4.z, a4.w};
            float b[4] = {b4.x, b4.y, b4.z, b4.w};
#pragma unroll
            for (int i = 0; i < 4; i++)
#pragma unroll
                for (int j = 0; j < 4; j++) acc[i][j] += a[i] * b[j];
        }
        __syncthreads();
    }

#pragma unroll
    for (int i = 0; i < 4; i++) {
        const int m = m0 + ty * 4 + i;
        const int b = m >> 11;
        const int n = m & 2047;
#pragma unroll
        for (int j = 0; j < 4; j++) {
            const int c   = n0 + tx * 4 + j;
            const int h   = c / 192;
            const int r   = c % 192;
            const int sel = r >> 6;     // 0=k, 1=q, 2=v (reference split order)
            const int o   = r & 63;
            float val = acc[i][j] + bias[c];
            const size_t idx = (((size_t)(b * NHEAD + h) * SEQ) + n) * HDIM + o;
            if (sel == 0)      g_k[idx] = val;
            else if (sel == 1) g_q[idx] = val * 0.125f;
            else               g_v[idx] = val;
        }
    }
}

// ---------------------------------------------------------------------------
// Causal flash attention: 1 query/thread, 128 queries/block, 32-key chunks.
// ---------------------------------------------------------------------------
__global__ __launch_bounds__(128)
void attn_kernel()
{
    const int bh = blockIdx.y;
    const int q0 = blockIdx.x * 128;
    const int qi = q0 + threadIdx.x;

    const float* __restrict__ Qg = g_q + (size_t)bh * SEQ * HDIM;
    const float* __restrict__ Kg = g_k + (size_t)bh * SEQ * HDIM;
    const float* __restrict__ Vg = g_v + (size_t)bh * SEQ * HDIM;

    float q[HDIM];
#pragma unroll
    for (int d = 0; d < HDIM; d += 4) {
        float4 v = *(const float4*)&Qg[(size_t)qi * HDIM + d];
        q[d] = v.x; q[d + 1] = v.y; q[d + 2] = v.z; q[d + 3] = v.w;
    }

    float acc[HDIM];
#pragma unroll
    for (int d = 0; d < HDIM; d++) acc[d] = 0.f;
    float mrun = -1e30f;
    float lrun = 0.f;

    __shared__ float Ks[32][HDIM];
    __shared__ float Vs[32][HDIM];

    const int kend = q0 + 128;
    for (int s0 = 0; s0 < kend; s0 += 32) {
        {
            const int t = threadIdx.x;
#pragma unroll
            for (int i = 0; i < 4; i++) {
                const int f   = i * 128 + t;
                const int row = f >> 4;
                const int col = (f & 15) * 4;
                *(float4*)&Ks[row][col] = *(const float4*)&Kg[(size_t)(s0 + row) * HDIM + col];
                *(float4*)&Vs[row][col] = *(const float4*)&Vg[(size_t)(s0 + row) * HDIM + col];
            }
        }
        __syncthreads();

        float p[32];
        float cmax = -1e30f;
#pragma unroll
        for (int kk = 0; kk < 32; kk++) {
            float s = 0.f;
#pragma unroll
            for (int d4 = 0; d4 < 16; d4++) {
                float4 kv = *(const float4*)&Ks[kk][d4 * 4];
                s += q[d4 * 4 + 0] * kv.x;
                s += q[d4 * 4 + 1] * kv.y;
                s += q[d4 * 4 + 2] * kv.z;
                s += q[d4 * 4 + 3] * kv.w;
            }
            s = (s0 + kk <= qi) ? s : -1e30f;
            p[kk] = s;
            cmax = fmaxf(cmax, s);
        }

        const float mnew  = fmaxf(mrun, cmax);
        const float alpha = __expf(mrun - mnew);
        float lsum = 0.f;
#pragma unroll
        for (int kk = 0; kk < 32; kk++) {
            p[kk] = __expf(p[kk] - mnew);
            lsum += p[kk];
        }
        lrun = lrun * alpha + lsum;
#pragma unroll
        for (int d = 0; d < HDIM; d++) acc[d] *= alpha;

#pragma unroll
        for (int kk = 0; kk < 32; kk++) {
            const float pv = p[kk];
#pragma unroll
            for (int d4 = 0; d4 < 16; d4++) {
                float4 vv = *(const float4*)&Vs[kk][d4 * 4];
                acc[d4 * 4 + 0] += pv * vv.x;
                acc[d4 * 4 + 1] += pv * vv.y;
                acc[d4 * 4 + 2] += pv * vv.z;
                acc[d4 * 4 + 3] += pv * vv.w;
            }
        }
        mrun = mnew;
        __syncthreads();
    }

    const float inv = 1.f / lrun;
    const int b = bh / NHEAD;
    const int h = bh % NHEAD;
    float* out = g_sa + ((size_t)(b * SEQ + qi)) * DMODEL + h * HDIM;
#pragma unroll
    for (int d = 0; d < HDIM; d += 4) {
        float4 v;
        v.x = acc[d] * inv;     v.y = acc[d + 1] * inv;
        v.z = acc[d + 2] * inv; v.w = acc[d + 3] * inv;
        *(float4*)&out[d] = v;
    }
}

// ---------------------------------------------------------------------------
// GEMM 2: output projection from g_sa.  out[m,c] = sum_d SA[m,d]*Wp[c,d]+bias[c]
// ---------------------------------------------------------------------------
__global__ __launch_bounds__(256)
void gemm_proj_kernel(const float* __restrict__ W,
                      const float* __restrict__ bias,
                      float* __restrict__ out)
{
    __shared__ float As[16][68];
    __shared__ float Bs[16][68];

    const int tx = threadIdx.x % 16;
    const int ty = threadIdx.x / 16;
    const int m0 = blockIdx.y * 64;
    const int n0 = blockIdx.x * 64;

    float acc[4][4];
#pragma unroll
    for (int i = 0; i < 4; i++)
#pragma unroll
        for (int j = 0; j < 4; j++) acc[i][j] = 0.f;

    for (int k0 = 0; k0 < DMODEL; k0 += 16) {
        {
            const int t   = threadIdx.x;
            const int row = t >> 2;
            const int kq  = (t & 3) * 4;
            float4 a = *(const float4*)&g_sa[(size_t)(m0 + row) * DMODEL + k0 + kq];
            As[kq + 0][row] = a.x; As[kq + 1][row] = a.y;
            As[kq + 2][row] = a.z; As[kq + 3][row] = a.w;
            float4 b = *(const float4*)&W[(size_t)(n0 + row) * DMODEL + k0 + kq];
            Bs[kq + 0][row] = b.x; Bs[kq + 1][row] = b.y;
            Bs[kq + 2][row] = b.z; Bs[kq + 3][row] = b.w;
        }
        __syncthreads();

#pragma unroll
        for (int k = 0; k < 16; k++) {
            float4 a4 = *(const float4*)&As[k][ty * 4];
            float4 b4 = *(const float4*)&Bs[k][tx * 4];
            float a[4] = {a4.x, a4.y, a4.z, a4.w};
            float b[4] = {b4.x, b4.y, b4.z, b4.w};
#pragma unroll
            for (int i = 0; i < 4; i++)
#pragma unroll
                for (int j = 0; j < 4; j++) acc[i][j] += a[i] * b[j];
        }
        __syncthreads();
    }

#pragma unroll
    for (int i = 0; i < 4; i++) {
        const int m = m0 + ty * 4 + i;
#pragma unroll
        for (int j = 0; j < 4; j++) {
            const int c = n0 + tx * 4 + j;
            out[(size_t)m * DMODEL + c] = acc[i][j] + bias[c];
        }
    }
}

extern "C" void kernel_launch(void* const* d_in, const int* in_sizes, int n_in,
                              void* d_out, int out_size)
{
    const float* x      = (const float*)d_in[0];  // [B, N, D]
    const float* W_kqv  = (const float*)d_in[1];  // [H, 3*HD, D]
    const float* b_kqv  = (const float*)d_in[2];  // [H, 3*HD]
    const float* W_proj = (const float*)d_in[3];  // [D, D]
    const float* b_proj = (const float*)d_in[4];  // [D]
    float* out = (float*)d_out;

    (void)in_sizes; (void)n_in; (void)out_size;

    {
        dim3 grid(QKV_COLS / 64, M_ROWS / 64);    // 36 x 64
        gemm_qkv_kernel<<<grid, 256>>>(x, W_kqv, b_kqv);
    }
    {
        dim3 grid(SEQ / 128, BATCH * NHEAD);      // 16 x 24
        attn_kernel<<<grid, 128>>>();
    }
    {
        dim3 grid(DMODEL / 64, M_ROWS / 64);      // 12 x 64
        gemm_proj_kernel<<<grid, 256>>>(W_proj, b_proj, out);
    }
}

// round 2
// speedup vs baseline: 1.1975x; 1.1975x over previous
#include <cuda_runtime.h>
#include <cuda_bf16.h>
#include <math.h>

#define BATCH 2
#define SEQ   2048
#define DMODEL 768
#define NHEAD 12
#define HDIM  64
#define M_ROWS (BATCH * SEQ)          // 4096
#define QKV_COLS (NHEAD * 3 * HDIM)   // 2304

typedef unsigned long long ull;

__device__ float g_q [BATCH * NHEAD * SEQ * HDIM];
__device__ float g_k [BATCH * NHEAD * SEQ * HDIM];
__device__ float g_v [BATCH * NHEAD * SEQ * HDIM];
__device__ float g_sa[M_ROWS * DMODEL];

// ---------------- packed f32x2 helpers (Blackwell FFMA2 path) ----------------
__device__ __forceinline__ ull pack2(float x, float y) {
    ull r;
    asm("mov.b64 %0, {%1, %2};" : "=l"(r)
        : "r"(__float_as_uint(x)), "r"(__float_as_uint(y)));
    return r;
}
__device__ __forceinline__ ull dup2(float x) { return pack2(x, x); }
__device__ __forceinline__ void fma2(ull& d, ull a, ull b) {
    asm("fma.rn.f32x2 %0, %1, %2, %0;" : "+l"(d) : "l"(a), "l"(b));
}
__device__ __forceinline__ ull mul2(ull a, ull b) {
    ull r;
    asm("mul.rn.f32x2 %0, %1, %2;" : "=l"(r) : "l"(a), "l"(b));
    return r;
}
__device__ __forceinline__ void unpack2(ull v, float& x, float& y) {
    unsigned a, b;
    asm("mov.b64 {%0, %1}, %2;" : "=r"(a), "=r"(b) : "l"(v));
    x = __uint_as_float(a); y = __uint_as_float(b);
}

// =============================================================================
// GEMM core: 128x128 tile, 256 threads, 8x8 microtile via f32x2, K-chunk 16,
// register-prefetch software pipeline.
// Thread map: ty = t/16 (m-sub = ty*8), tx = t%16 (n-sub = tx*8).
// Smem: [16][132] k-major (transposed on store).
// =============================================================================
#define KCH 16
#define LDP 132   // padded row length (floats); keeps float4 alignment

__device__ __forceinline__ void stage_ldg(const float* __restrict__ src, int ld,
                                          int r0, int k0, int t,
                                          float4& v0, float4& v1)
{
    // f = t + i*256 ; row = f>>2 ; kq = (f&3)*4   (coalesced along k)
    int f0 = t,        row0 = f0 >> 2, kq0 = (f0 & 3) * 4;
    int f1 = t + 256,  row1 = f1 >> 2, kq1 = (f1 & 3) * 4;
    v0 = *(const float4*)&src[(size_t)(r0 + row0) * ld + k0 + kq0];
    v1 = *(const float4*)&src[(size_t)(r0 + row1) * ld + k0 + kq1];
}

__device__ __forceinline__ void stage_sts(float (*S)[LDP], int t,
                                          const float4& v0, const float4& v1)
{
    int f0 = t,       row0 = f0 >> 2, kq0 = (f0 & 3) * 4;
    int f1 = t + 256, row1 = f1 >> 2, kq1 = (f1 & 3) * 4;
    S[kq0 + 0][row0] = v0.x; S[kq0 + 1][row0] = v0.y;
    S[kq0 + 2][row0] = v0.z; S[kq0 + 3][row0] = v0.w;
    S[kq1 + 0][row1] = v1.x; S[kq1 + 1][row1] = v1.y;
    S[kq1 + 2][row1] = v1.z; S[kq1 + 3][row1] = v1.w;
}

__device__ __forceinline__ void gemm_mainloop(const float* __restrict__ A,
                                              const float* __restrict__ B,
                                              int m0, int n0,
                                              float (*As)[LDP], float (*Bs)[LDP],
                                              int ty, int tx, int t,
                                              ull acc[8][4])
{
#pragma unroll
    for (int i = 0; i < 8; i++)
#pragma unroll
        for (int j = 0; j < 4; j++) acc[i][j] = 0ULL;

    float4 pa0, pa1, pb0, pb1;
    stage_ldg(A, DMODEL, m0, 0, t, pa0, pa1);
    stage_ldg(B, DMODEL, n0, 0, t, pb0, pb1);

    for (int k0 = 0; k0 < DMODEL; k0 += KCH) {
        stage_sts(As, t, pa0, pa1);
        stage_sts(Bs, t, pb0, pb1);
        __syncthreads();

        if (k0 + KCH < DMODEL) {
            stage_ldg(A, DMODEL, m0, k0 + KCH, t, pa0, pa1);
            stage_ldg(B, DMODEL, n0, k0 + KCH, t, pb0, pb1);
        }

#pragma unroll
        for (int k = 0; k < KCH; k++) {
            float4 a0 = *(const float4*)&As[k][ty * 8];
            float4 a1 = *(const float4*)&As[k][ty * 8 + 4];
            ulonglong2 bq0 = *(const ulonglong2*)&Bs[k][tx * 8];
            ulonglong2 bq1 = *(const ulonglong2*)&Bs[k][tx * 8 + 4];
            ull b2[4] = {bq0.x, bq0.y, bq1.x, bq1.y};
            ull ad[8];
            ad[0] = dup2(a0.x); ad[1] = dup2(a0.y);
            ad[2] = dup2(a0.z); ad[3] = dup2(a0.w);
            ad[4] = dup2(a1.x); ad[5] = dup2(a1.y);
            ad[6] = dup2(a1.z); ad[7] = dup2(a1.w);
#pragma unroll
            for (int i = 0; i < 8; i++)
#pragma unroll
                for (int j = 0; j < 4; j++)
                    fma2(acc[i][j], ad[i], b2[j]);
        }
        __syncthreads();
    }
}

// ---------------------------------------------------------------------------
// GEMM 1: QKV projection + scatter epilogue into g_k/g_q/g_v ([B,H,N,HD]).
// ---------------------------------------------------------------------------
__global__ __launch_bounds__(256)
void gemm_qkv_kernel(const float* __restrict__ X,
                     const float* __restrict__ W,
                     const float* __restrict__ bias)
{
    __shared__ __align__(16) float As[KCH][LDP];
    __shared__ __align__(16) float Bs[KCH][LDP];

    const int t  = threadIdx.x;
    const int tx = t % 16, ty = t / 16;
    const int m0 = blockIdx.y * 128;
    const int n0 = blockIdx.x * 128;

    ull acc[8][4];
    gemm_mainloop(X, W, m0, n0, As, Bs, ty, tx, t, acc);

#pragma unroll
    for (int i = 0; i < 8; i++) {
        const int m = m0 + ty * 8 + i;
        const int b = m >> 11;
        const int n = m & 2047;
#pragma unroll
        for (int jp = 0; jp < 4; jp++) {
            float v0, v1;
            unpack2(acc[i][jp], v0, v1);
            float vv[2] = {v0, v1};
#pragma unroll
            for (int e = 0; e < 2; e++) {
                const int c   = n0 + tx * 8 + jp * 2 + e;
                const int h   = c / 192;
                const int r   = c % 192;
                const int sel = r >> 6;     // 0=k, 1=q, 2=v
                const int o   = r & 63;
                float val = vv[e] + bias[c];
                const size_t idx = (((size_t)(b * NHEAD + h) * SEQ) + n) * HDIM + o;
                if (sel == 0)      g_k[idx] = val;
                else if (sel == 1) g_q[idx] = val * 0.125f;
                else               g_v[idx] = val;
            }
        }
    }
}

// ---------------------------------------------------------------------------
// GEMM 2: output projection (reads g_sa).
// ---------------------------------------------------------------------------
__global__ __launch_bounds__(256)
void gemm_proj_kernel(const float* __restrict__ W,
                      const float* __restrict__ bias,
                      float* __restrict__ out)
{
    __shared__ __align__(16) float As[KCH][LDP];
    __shared__ __align__(16) float Bs[KCH][LDP];

    const int t  = threadIdx.x;
    const int tx = t % 16, ty = t / 16;
    const int m0 = blockIdx.y * 128;
    const int n0 = blockIdx.x * 128;

    ull acc[8][4];
    gemm_mainloop(g_sa, W, m0, n0, As, Bs, ty, tx, t, acc);

#pragma unroll
    for (int i = 0; i < 8; i++) {
        const int m = m0 + ty * 8 + i;
#pragma unroll
        for (int jp = 0; jp < 4; jp++) {
            float v0, v1;
            unpack2(acc[i][jp], v0, v1);
            const int c = n0 + tx * 8 + jp * 2;
            float2 o2 = make_float2(v0 + bias[c], v1 + bias[c + 1]);
            *(float2*)&out[(size_t)m * DMODEL + c] = o2;
        }
    }
}

// ---------------------------------------------------------------------------
// Causal flash attention with packed f32x2 math.
// 1 query/thread, 128 queries/block, 32-key smem chunks.
// ---------------------------------------------------------------------------
__global__ __launch_bounds__(128)
void attn_kernel()
{
    const int bh = blockIdx.y;
    const int q0 = blockIdx.x * 128;
    const int qi = q0 + threadIdx.x;

    const float* __restrict__ Qg = g_q + (size_t)bh * SEQ * HDIM;
    const float* __restrict__ Kg = g_k + (size_t)bh * SEQ * HDIM;
    const float* __restrict__ Vg = g_v + (size_t)bh * SEQ * HDIM;

    // query row as 32 f32x2
    ull q2[32];
    {
        const ulonglong2* qp = (const ulonglong2*)&Qg[(size_t)qi * HDIM];
#pragma unroll
        for (int d = 0; d < 16; d++) {
            ulonglong2 v = qp[d];
            q2[2 * d] = v.x; q2[2 * d + 1] = v.y;
        }
    }

    ull acc2[32];
#pragma unroll
    for (int d = 0; d < 32; d++) acc2[d] = 0ULL;
    float mrun = -1e30f;
    float lrun = 0.f;

    __shared__ __align__(16) float Ks[32][HDIM];
    __shared__ __align__(16) float Vs[32][HDIM];

    const int kend = q0 + 128;
    for (int s0 = 0; s0 < kend; s0 += 32) {
        {
            const int t = threadIdx.x;
#pragma unroll
            for (int i = 0; i < 4; i++) {
                const int f   = i * 128 + t;
                const int row = f >> 4;
                const int col = (f & 15) * 4;
                *(float4*)&Ks[row][col] = *(const float4*)&Kg[(size_t)(s0 + row) * HDIM + col];
                *(float4*)&Vs[row][col] = *(const float4*)&Vg[(size_t)(s0 + row) * HDIM + col];
            }
        }
        __syncthreads();

        float p[32];
        float cmax = -1e30f;
#pragma unroll
        for (int kk = 0; kk < 32; kk++) {
            const ulonglong2* kp = (const ulonglong2*)&Ks[kk][0];
            ull sa = 0ULL, sb = 0ULL;
#pragma unroll
            for (int d = 0; d < 16; d++) {
                ulonglong2 kv = kp[d];
                fma2(sa, q2[2 * d],     kv.x);
                fma2(sb, q2[2 * d + 1], kv.y);
            }
            float a0, a1, b0, b1;
            unpack2(sa, a0, a1);
            unpack2(sb, b0, b1);
            float s = (a0 + a1) + (b0 + b1);
            s = (s0 + kk <= qi) ? s : -1e30f;
            p[kk] = s;
            cmax = fmaxf(cmax, s);
        }

        const float mnew  = fmaxf(mrun, cmax);
        const float alpha = __expf(mrun - mnew);
        float lsum = 0.f;
#pragma unroll
        for (int kk = 0; kk < 32; kk++) {
            p[kk] = __expf(p[kk] - mnew);
            lsum += p[kk];
        }
        lrun = lrun * alpha + lsum;
        const ull a2 = dup2(alpha);
#pragma unroll
        for (int d = 0; d < 32; d++) acc2[d] = mul2(acc2[d], a2);

#pragma unroll
        for (int kk = 0; kk < 32; kk++) {
            const ull pv = dup2(p[kk]);
            const ulonglong2* vp = (const ulonglong2*)&Vs[kk][0];
#pragma unroll
            for (int d = 0; d < 16; d++) {
                ulonglong2 vv = vp[d];
                fma2(acc2[2 * d],     pv, vv.x);
                fma2(acc2[2 * d + 1], pv, vv.y);
            }
        }
        mrun = mnew;
        __syncthreads();
    }

    const float inv = 1.f / lrun;
    const int b = bh / NHEAD;
    const int h = bh % NHEAD;
    float* out = g_sa + ((size_t)(b * SEQ + qi)) * DMODEL + h * HDIM;
#pragma unroll
    for (int d = 0; d < 16; d++) {
        float x0, x1, y0, y1;
        unpack2(acc2[2 * d], x0, x1);
        unpack2(acc2[2 * d + 1], y0, y1);
        float4 v = make_float4(x0 * inv, x1 * inv, y0 * inv, y1 * inv);
        *(float4*)&out[d * 4] = v;
    }
}

// ---------------------------------------------------------------------------
extern "C" void kernel_launch(void* const* d_in, const int* in_sizes, int n_in,
                              void* d_out, int out_size)
{
    const float* x      = (const float*)d_in[0];  // [B, N, D]
    const float* W_kqv  = (const float*)d_in[1];  // [H, 3*HD, D]
    const float* b_kqv  = (const float*)d_in[2];  // [H, 3*HD]
    const float* W_proj = (const float*)d_in[3];  // [D, D]
    const float* b_proj = (const float*)d_in[4];  // [D]
    float* out = (float*)d_out;

    (void)in_sizes; (void)n_in; (void)out_size;

    {
        dim3 grid(QKV_COLS / 128, M_ROWS / 128);  // 18 x 32
        gemm_qkv_kernel<<<grid, 256>>>(x, W_kqv, b_kqv);
    }
    {
        dim3 grid(SEQ / 128, BATCH * NHEAD);      // 16 x 24
        attn_kernel<<<grid, 128>>>();
    }
    {
        dim3 grid(DMODEL / 128, M_ROWS / 128);    // 6 x 32
        gemm_proj_kernel<<<grid, 256>>>(W_proj, b_proj, out);
    }
}

// round 4
// speedup vs baseline: 1.6903x; 1.4115x over previous
#include <cuda_runtime.h>
#include <cuda_bf16.h>
#include <math.h>
#include <stdint.h>

#define BATCH 2
#define SEQ   2048
#define DMODEL 768
#define NHEAD 12
#define HDIM  64
#define M_ROWS (BATCH * SEQ)          // 4096
#define QKV_COLS (NHEAD * 3 * HDIM)   // 2304
#define K2 2304                       // expanded K' = 3*768
#define KCHUNK 32
#define NCHUNKS (K2 / KCHUNK)         // 72
#define APITCH 40                     // smem row pitch in bf16 (80B, conflict-free ldmatrix)

typedef unsigned long long ull;

// ------------------------------ device scratch ------------------------------
__device__ float g_q [BATCH * NHEAD * SEQ * HDIM];
__device__ float g_k [BATCH * NHEAD * SEQ * HDIM];
__device__ float g_v [BATCH * NHEAD * SEQ * HDIM];
__device__ float g_sa[M_ROWS * DMODEL];

__device__ __nv_bfloat16 g_xs [(size_t)M_ROWS   * K2]; // X  split  [hi|hi|lo]
__device__ __nv_bfloat16 g_wk [(size_t)QKV_COLS * K2]; // Wkqv split[hi|lo|hi]
__device__ __nv_bfloat16 g_wp [(size_t)DMODEL   * K2]; // Wproj split[hi|lo|hi]
__device__ __nv_bfloat16 g_sas[(size_t)M_ROWS   * K2]; // SA split  [hi|hi|lo]

// ------------------------- packed f32x2 (attention) -------------------------
__device__ __forceinline__ ull pack2(float x, float y) {
    ull r;
    asm("mov.b64 %0, {%1, %2};" : "=l"(r)
        : "r"(__float_as_uint(x)), "r"(__float_as_uint(y)));
    return r;
}
__device__ __forceinline__ ull dup2(float x) { return pack2(x, x); }
__device__ __forceinline__ void fma2(ull& d, ull a, ull b) {
    asm("fma.rn.f32x2 %0, %1, %2, %0;" : "+l"(d) : "l"(a), "l"(b));
}
__device__ __forceinline__ ull mul2(ull a, ull b) {
    ull r;
    asm("mul.rn.f32x2 %0, %1, %2;" : "=l"(r) : "l"(a), "l"(b));
    return r;
}
__device__ __forceinline__ void unpack2(ull v, float& x, float& y) {
    unsigned a, b;
    asm("mov.b64 {%0, %1}, %2;" : "=r"(a), "=r"(b) : "l"(v));
    x = __uint_as_float(a); y = __uint_as_float(b);
}

// ------------------------------ PTX helpers ---------------------------------
__device__ __forceinline__ uint32_t smem_u32(const void* p) {
    uint32_t a;
    asm("{ .reg .u64 t; cvta.to.shared.u64 t, %1; cvt.u32.u64 %0, t; }"
        : "=r"(a) : "l"(p));
    return a;
}
__device__ __forceinline__ void cp16(uint32_t dst, const void* src) {
    asm volatile("cp.async.cg.shared.global [%0], [%1], 16;"
                 :: "r"(dst), "l"(src) : "memory");
}
#define CP_COMMIT() asm volatile("cp.async.commit_group;" ::: "memory")
#define CP_WAIT1()  asm volatile("cp.async.wait_group 1;" ::: "memory")
#define CP_WAIT0()  asm volatile("cp.async.wait_group 0;" ::: "memory")

__device__ __forceinline__ void ldsm4(uint32_t addr, uint32_t r[4]) {
    asm volatile("ldmatrix.sync.aligned.m8n8.x4.shared.b16 {%0,%1,%2,%3}, [%4];"
                 : "=r"(r[0]), "=r"(r[1]), "=r"(r[2]), "=r"(r[3]) : "r"(addr));
}
__device__ __forceinline__ void mma16816(float d[4], const uint32_t a[4],
                                         uint32_t b0, uint32_t b1) {
    asm volatile(
        "mma.sync.aligned.m16n8k16.row.col.f32.bf16.bf16.f32 "
        "{%0,%1,%2,%3}, {%4,%5,%6,%7}, {%8,%9}, {%0,%1,%2,%3};"
        : "+f"(d[0]), "+f"(d[1]), "+f"(d[2]), "+f"(d[3])
        : "r"(a[0]), "r"(a[1]), "r"(a[2]), "r"(a[3]), "r"(b0), "r"(b1));
}

// =============================================================================
// HMMA GEMM core: 128x128 tile, 256 threads (8 warps, 4x2), K-chunk 32,
// 2-stage cp.async pipeline. C = A[mx2304] * B[nx2304]^T (both K-major bf16).
// =============================================================================
struct GemmSmem {
    __nv_bfloat16 A[2][128][APITCH];
    __nv_bfloat16 B[2][128][APITCH];
};

__device__ __forceinline__ void gemm_load_chunk(GemmSmem* sm, int buf,
                                                const __nv_bfloat16* __restrict__ A,
                                                const __nv_bfloat16* __restrict__ B,
                                                int m0, int n0, int k0, int t)
{
#pragma unroll
    for (int i = 0; i < 2; i++) {
        const int idx = i * 256 + t;
        const int row = idx >> 2;
        const int c   = (idx & 3) * 8;       // bf16 elements (16B)
        cp16(smem_u32(&sm->A[buf][row][c]), &A[(size_t)(m0 + row) * K2 + k0 + c]);
        cp16(smem_u32(&sm->B[buf][row][c]), &B[(size_t)(n0 + row) * K2 + k0 + c]);
    }
}

__device__ __forceinline__ void gemm_mainloop(GemmSmem* sm,
                                              const __nv_bfloat16* __restrict__ A,
                                              const __nv_bfloat16* __restrict__ B,
                                              int m0, int n0, float acc[2][8][4])
{
    const int t    = threadIdx.x;
    const int lane = t & 31;
    const int wid  = t >> 5;
    const int wm   = wid >> 1;       // 0..3 -> rows wm*32
    const int wn   = wid & 1;        // 0..1 -> cols wn*64

#pragma unroll
    for (int i = 0; i < 2; i++)
#pragma unroll
        for (int j = 0; j < 8; j++)
#pragma unroll
            for (int e = 0; e < 4; e++) acc[i][j][e] = 0.f;

    // ldmatrix lane geometry
    const int g  = lane >> 3;
    const int l8 = lane & 7;
    // A x4: M0 rows0-7/k0-7, M1 rows8-15/k0-7, M2 rows0-7/k8-15, M3 rows8-15/k8-15
    const int a_row = l8 + ((g & 1) << 3);
    const int a_col = (g >> 1) << 3;
    // B x4: M0 n0-7/k0-7, M1 n0-7/k8-15, M2 n8-15/k0-7, M3 n8-15/k8-15
    const int b_row = l8 + ((g >> 1) << 3);
    const int b_col = (g & 1) << 3;

    gemm_load_chunk(sm, 0, A, B, m0, n0, 0, t);
    CP_COMMIT();

    for (int ic = 0; ic < NCHUNKS; ic++) {
        const int buf = ic & 1;
        if (ic + 1 < NCHUNKS) {
            gemm_load_chunk(sm, buf ^ 1, A, B, m0, n0, (ic + 1) * KCHUNK, t);
            CP_COMMIT();
            CP_WAIT1();
        } else {
            CP_WAIT0();
        }
        __syncthreads();

#pragma unroll
        for (int ks = 0; ks < 2; ks++) {
            const int k0 = ks * 16;
            uint32_t af[2][4];
#pragma unroll
            for (int mi = 0; mi < 2; mi++)
                ldsm4(smem_u32(&sm->A[buf][wm * 32 + mi * 16 + a_row][k0 + a_col]),
                      af[mi]);
            uint32_t bf[4][4];
#pragma unroll
            for (int np = 0; np < 4; np++)
                ldsm4(smem_u32(&sm->B[buf][wn * 64 + np * 16 + b_row][k0 + b_col]),
                      bf[np]);
#pragma unroll
            for (int mi = 0; mi < 2; mi++)
#pragma unroll
                for (int np = 0; np < 4; np++) {
                    mma16816(acc[mi][2 * np],     af[mi], bf[np][0], bf[np][1]);
                    mma16816(acc[mi][2 * np + 1], af[mi], bf[np][2], bf[np][3]);
                }
        }
        __syncthreads();
    }
}

// ---------------------------- GEMM 1: QKV + scatter --------------------------
__global__ __launch_bounds__(256, 2)
void gemm_qkv_tc(const float* __restrict__ bias)
{
    __shared__ GemmSmem sm;
    const int m0 = blockIdx.y * 128, n0 = blockIdx.x * 128;

    float acc[2][8][4];
    gemm_mainloop(&sm, g_xs, g_wk, m0, n0, acc);

    const int t = threadIdx.x, lane = t & 31, wid = t >> 5;
    const int wm = wid >> 1, wn = wid & 1;

#pragma unroll
    for (int mi = 0; mi < 2; mi++) {
        const int r0 = m0 + wm * 32 + mi * 16 + (lane >> 2);
#pragma unroll
        for (int nf = 0; nf < 8; nf++) {
            const int c   = n0 + wn * 64 + nf * 8 + (lane & 3) * 2;
            const int h   = c / 192;
            const int rr  = c % 192;
            const int sel = rr >> 6;
            const int o   = rr & 63;
            const float scale = (sel == 1) ? 0.125f : 1.0f;
            float* base = (sel == 0) ? g_k : (sel == 1) ? g_q : g_v;
            const float bx = bias[c], by = bias[c + 1];
#pragma unroll
            for (int rh = 0; rh < 2; rh++) {
                const int m  = r0 + rh * 8;
                const int bb = m >> 11, n = m & 2047;
                const size_t i0 = (((size_t)(bb * NHEAD + h) * SEQ) + n) * HDIM + o;
                float2 v;
                v.x = (acc[mi][nf][2 * rh + 0] + bx) * scale;
                v.y = (acc[mi][nf][2 * rh + 1] + by) * scale;
                *(float2*)&base[i0] = v;
            }
        }
    }
}

// ---------------------------- GEMM 2: projection -----------------------------
__global__ __launch_bounds__(256, 2)
void gemm_proj_tc(const float* __restrict__ bias, float* __restrict__ out)
{
    __shared__ GemmSmem sm;
    const int m0 = blockIdx.y * 128, n0 = blockIdx.x * 128;

    float acc[2][8][4];
    gemm_mainloop(&sm, g_sas, g_wp, m0, n0, acc);

    const int t = threadIdx.x, lane = t & 31, wid = t >> 5;
    const int wm = wid >> 1, wn = wid & 1;

#pragma unroll
    for (int mi = 0; mi < 2; mi++) {
        const int r0 = m0 + wm * 32 + mi * 16 + (lane >> 2);
#pragma unroll
        for (int nf = 0; nf < 8; nf++) {
            const int c = n0 + wn * 64 + nf * 8 + (lane & 3) * 2;
            const float bx = bias[c], by = bias[c + 1];
#pragma unroll
            for (int rh = 0; rh < 2; rh++) {
                const int m = r0 + rh * 8;
                float2 v;
                v.x = acc[mi][nf][2 * rh + 0] + bx;
                v.y = acc[mi][nf][2 * rh + 1] + by;
                *(float2*)&out[(size_t)m * DMODEL + c] = v;
            }
        }
    }
}

// ---------------------------- conversion kernel -----------------------------
// in [R x 768] fp32 -> out [R x 2304] bf16 split blocks.
// pattern 0 (A-side): [hi | hi | lo] ; pattern 1 (B-side): [hi | lo | hi]
__global__ __launch_bounds__(256)
void convert_split_kernel(const float* __restrict__ in, int out_sel, int pattern)
{
    __nv_bfloat16* out = (out_sel == 0) ? g_xs
                       : (out_sel == 1) ? g_wk
                       : (out_sel == 2) ? g_wp : g_sas;
    const float* src = in ? in : g_sa;

    const size_t gid = (size_t)blockIdx.x * 256 + threadIdx.x;   // one float4
    const size_t r = gid / 192;
    const int    c = (int)(gid % 192) * 4;
    float4 x = *(const float4*)&src[r * 768 + c];

    union BF4 { __nv_bfloat16 b[4]; uint2 u; };
    BF4 hi, lo;
    float xv[4] = {x.x, x.y, x.z, x.w};
#pragma unroll
    for (int i = 0; i < 4; i++) {
        hi.b[i] = __float2bfloat16(xv[i]);
        lo.b[i] = __float2bfloat16(xv[i] - __bfloat162float(hi.b[i]));
    }
    __nv_bfloat16* row = out + r * K2;
    *(uint2*)(row + c) = hi.u;
    if (pattern == 0) {
        *(uint2*)(row + 768  + c) = hi.u;
        *(uint2*)(row + 1536 + c) = lo.u;
    } else {
        *(uint2*)(row + 768  + c) = lo.u;
        *(uint2*)(row + 1536 + c) = hi.u;
    }
}

// ---------------------------------------------------------------------------
// Causal flash attention (f32x2 math). Reads g_q/g_k/g_v fp32.
// ---------------------------------------------------------------------------
__global__ __launch_bounds__(128)
void attn_kernel()
{
    const int bh = blockIdx.y;
    const int q0 = blockIdx.x * 128;
    const int qi = q0 + threadIdx.x;

    const float* __restrict__ Qg = g_q + (size_t)bh * SEQ * HDIM;
    const float* __restrict__ Kg = g_k + (size_t)bh * SEQ * HDIM;
    const float* __restrict__ Vg = g_v + (size_t)bh * SEQ * HDIM;

    ull q2[32];
    {
        const ulonglong2* qp = (const ulonglong2*)&Qg[(size_t)qi * HDIM];
#pragma unroll
        for (int d = 0; d < 16; d++) {
            ulonglong2 v = qp[d];
            q2[2 * d] = v.x; q2[2 * d + 1] = v.y;
        }
    }

    ull acc2[32];
#pragma unroll
    for (int d = 0; d < 32; d++) acc2[d] = 0ULL;
    float mrun = -1e30f;
    float lrun = 0.f;

    __shared__ __align__(16) float Ks[32][HDIM];
    __shared__ __align__(16) float Vs[32][HDIM];

    const int kend = q0 + 128;
    for (int s0 = 0; s0 < kend; s0 += 32) {
        {
            const int t = threadIdx.x;
#pragma unroll
            for (int i = 0; i < 4; i++) {
                const int f   = i * 128 + t;
                const int row = f >> 4;
                const int col = (f & 15) * 4;
                *(float4*)&Ks[row][col] = *(const float4*)&Kg[(size_t)(s0 + row) * HDIM + col];
                *(float4*)&Vs[row][col] = *(const float4*)&Vg[(size_t)(s0 + row) * HDIM + col];
            }
        }
        __syncthreads();

        float p[32];
        float cmax = -1e30f;
#pragma unroll
        for (int kk = 0; kk < 32; kk++) {
            const ulonglong2* kp = (const ulonglong2*)&Ks[kk][0];
            ull sa = 0ULL, sbv = 0ULL;
#pragma unroll
            for (int d = 0; d < 16; d++) {
                ulonglong2 kv = kp[d];
                fma2(sa,  q2[2 * d],     kv.x);
                fma2(sbv, q2[2 * d + 1], kv.y);
            }
            float a0, a1, b0, b1;
            unpack2(sa, a0, a1);
            unpack2(sbv, b0, b1);
            float s = (a0 + a1) + (b0 + b1);
            s = (s0 + kk <= qi) ? s : -1e30f;
            p[kk] = s;
            cmax = fmaxf(cmax, s);
        }

        const float mnew  = fmaxf(mrun, cmax);
        const float alpha = __expf(mrun - mnew);
        float lsum = 0.f;
#pragma unroll
        for (int kk = 0; kk < 32; kk++) {
            p[kk] = __expf(p[kk] - mnew);
            lsum += p[kk];
        }
        lrun = lrun * alpha + lsum;
        const ull a2 = dup2(alpha);
#pragma unroll
        for (int d = 0; d < 32; d++) acc2[d] = mul2(acc2[d], a2);

#pragma unroll
        for (int kk = 0; kk < 32; kk++) {
            const ull pv = dup2(p[kk]);
            const ulonglong2* vp = (const ulonglong2*)&Vs[kk][0];
#pragma unroll
            for (int d = 0; d < 16; d++) {
                ulonglong2 vv = vp[d];
                fma2(acc2[2 * d],     pv, vv.x);
                fma2(acc2[2 * d + 1], pv, vv.y);
            }
        }
        mrun = mnew;
        __syncthreads();
    }

    const float inv = 1.f / lrun;
    const int b = bh / NHEAD;
    const int h = bh % NHEAD;
    float* outp = g_sa + ((size_t)(b * SEQ + qi)) * DMODEL + h * HDIM;
#pragma unroll
    for (int d = 0; d < 16; d++) {
        float x0, x1, y0, y1;
        unpack2(acc2[2 * d], x0, x1);
        unpack2(acc2[2 * d + 1], y0, y1);
        float4 v = make_float4(x0 * inv, x1 * inv, y0 * inv, y1 * inv);
        *(float4*)&outp[d * 4] = v;
    }
}

// ---------------------------------------------------------------------------
extern "C" void kernel_launch(void* const* d_in, const int* in_sizes, int n_in,
                              void* d_out, int out_size)
{
    const float* x      = (const float*)d_in[0];  // [B, N, D]
    const float* W_kqv  = (const float*)d_in[1];  // [H, 3*HD, D]
    const float* b_kqv  = (const float*)d_in[2];  // [H, 3*HD]
    const float* W_proj = (const float*)d_in[3];  // [D, D]
    const float* b_proj = (const float*)d_in[4];  // [D]
    float* out = (float*)d_out;

    (void)in_sizes; (void)n_in; (void)out_size;

    // split conversions
    convert_split_kernel<<<3072, 256>>>(x,      0, 0);  // X    -> g_xs  [hi|hi|lo]
    convert_split_kernel<<<1728, 256>>>(W_kqv,  1, 1);  // Wkqv -> g_wk  [hi|lo|hi]
    convert_split_kernel<<<576,  256>>>(W_proj, 2, 1);  // Wproj-> g_wp  [hi|lo|hi]

    // QKV projection on tensor cores (HMMA)
    {
        dim3 grid(QKV_COLS / 128, M_ROWS / 128);   // 18 x 32
        gemm_qkv_tc<<<grid, 256>>>(b_kqv);
    }
    // attention
    {
        dim3 grid(SEQ / 128, BATCH * NHEAD);       // 16 x 24
        attn_kernel<<<grid, 128>>>();
    }
    // SA split + output projection
    convert_split_kernel<<<3072, 256>>>(nullptr, 3, 0); // g_sa -> g_sas [hi|hi|lo]
    {
        dim3 grid(DMODEL / 128, M_ROWS / 128);     // 6 x 32
        gemm_proj_tc<<<grid, 256>>>(b_proj, out);
    }
}

// round 6
// speedup vs baseline: 3.2956x; 1.9498x over previous
#include <cuda_runtime.h>
#include <cuda_bf16.h>
#include <math.h>
#include <stdint.h>

#define BATCH 2
#define SEQ   2048
#define DMODEL 768
#define NHEAD 12
#define HDIM  64
#define M_ROWS (BATCH * SEQ)          // 4096
#define QKV_COLS (NHEAD * 3 * HDIM)   // 2304
#define K2 2304                       // expanded K' = 3*768
#define KCHUNK 32
#define NCHUNKS (K2 / KCHUNK)         // 72
#define APITCH 40                     // GEMM smem pitch in bf16 (rows are 32 wide)

// ------------------------------ device scratch ------------------------------
__device__ __nv_bfloat16 g_xs [(size_t)M_ROWS   * K2]; // X  split  [hi|hi|lo]
__device__ __nv_bfloat16 g_wk [(size_t)QKV_COLS * K2]; // Wkqv split[hi|lo|hi]
__device__ __nv_bfloat16 g_wp [(size_t)DMODEL   * K2]; // Wproj split[hi|lo|hi]
__device__ __nv_bfloat16 g_sas[(size_t)M_ROWS   * K2]; // SA split  [hi|hi|lo]

// Q/K/V bf16 hi/lo planes, layout [bh][n][64]
#define QKV_ELEMS ((size_t)BATCH * NHEAD * SEQ * HDIM)
__device__ __nv_bfloat16 g_qh[QKV_ELEMS], g_ql[QKV_ELEMS];
__device__ __nv_bfloat16 g_kh[QKV_ELEMS], g_kl[QKV_ELEMS];
__device__ __nv_bfloat16 g_vh[QKV_ELEMS], g_vl[QKV_ELEMS];

// ------------------------------ PTX helpers ---------------------------------
__device__ __forceinline__ uint32_t smem_u32(const void* p) {
    uint32_t a;
    asm("{ .reg .u64 t; cvta.to.shared.u64 t, %1; cvt.u32.u64 %0, t; }"
        : "=r"(a) : "l"(p));
    return a;
}
__device__ __forceinline__ void cp16(uint32_t dst, const void* src) {
    asm volatile("cp.async.cg.shared.global [%0], [%1], 16;"
                 :: "r"(dst), "l"(src) : "memory");
}
#define CP_COMMIT() asm volatile("cp.async.commit_group;" ::: "memory")
#define CP_WAIT1()  asm volatile("cp.async.wait_group 1;" ::: "memory")
#define CP_WAIT0()  asm volatile("cp.async.wait_group 0;" ::: "memory")

__device__ __forceinline__ void ldsm4(uint32_t addr, uint32_t r[4]) {
    asm volatile("ldmatrix.sync.aligned.m8n8.x4.shared.b16 {%0,%1,%2,%3}, [%4];"
                 : "=r"(r[0]), "=r"(r[1]), "=r"(r[2]), "=r"(r[3]) : "r"(addr));
}
__device__ __forceinline__ void ldsm4t(uint32_t addr, uint32_t r[4]) {
    asm volatile("ldmatrix.sync.aligned.m8n8.x4.trans.shared.b16 {%0,%1,%2,%3}, [%4];"
                 : "=r"(r[0]), "=r"(r[1]), "=r"(r[2]), "=r"(r[3]) : "r"(addr));
}
__device__ __forceinline__ void mma16816(float d[4], const uint32_t a[4],
                                         uint32_t b0, uint32_t b1) {
    asm volatile(
        "mma.sync.aligned.m16n8k16.row.col.f32.bf16.bf16.f32 "
        "{%0,%1,%2,%3}, {%4,%5,%6,%7}, {%8,%9}, {%0,%1,%2,%3};"
        : "+f"(d[0]), "+f"(d[1]), "+f"(d[2]), "+f"(d[3])
        : "r"(a[0]), "r"(a[1]), "r"(a[2]), "r"(a[3]), "r"(b0), "r"(b1));
}
// packed bf16x2 with lo = first memory element
__device__ __forceinline__ uint32_t packbf2(float lo, float hi) {
    uint32_t r;
    asm("cvt.rn.bf16x2.f32 %0, %1, %2;" : "=r"(r) : "f"(hi), "f"(lo));
    return r;
}

// split-store helper: hi/lo bf16x2 at 4B-aligned addresses
__device__ __forceinline__ void split_store(__nv_bfloat16* ph, __nv_bfloat16* pl,
                                            size_t idx, float f0, float f1) {
    __nv_bfloat16 h0 = __float2bfloat16(f0), h1 = __float2bfloat16(f1);
    float r0 = f0 - __bfloat162float(h0), r1 = f1 - __bfloat162float(h1);
    __nv_bfloat162 hv; hv.x = h0; hv.y = h1;
    __nv_bfloat162 lv; lv.x = __float2bfloat16(r0); lv.y = __float2bfloat16(r1);
    *(__nv_bfloat162*)&ph[idx] = hv;
    *(__nv_bfloat162*)&pl[idx] = lv;
}

// =============================================================================
// HMMA GEMM core (passed R4): 128x128 tile, 256 threads, K-chunk 32, 2-stage.
// =============================================================================
struct GemmSmem {
    __nv_bfloat16 A[2][128][APITCH];
    __nv_bfloat16 B[2][128][APITCH];
};

__device__ __forceinline__ void gemm_load_chunk(GemmSmem* sm, int buf,
                                                const __nv_bfloat16* __restrict__ A,
                                                const __nv_bfloat16* __restrict__ B,
                                                int m0, int n0, int k0, int t)
{
#pragma unroll
    for (int i = 0; i < 2; i++) {
        const int idx = i * 256 + t;
        const int row = idx >> 2;
        const int c   = (idx & 3) * 8;
        cp16(smem_u32(&sm->A[buf][row][c]), &A[(size_t)(m0 + row) * K2 + k0 + c]);
        cp16(smem_u32(&sm->B[buf][row][c]), &B[(size_t)(n0 + row) * K2 + k0 + c]);
    }
}

__device__ __forceinline__ void gemm_mainloop(GemmSmem* sm,
                                              const __nv_bfloat16* __restrict__ A,
                                              const __nv_bfloat16* __restrict__ B,
                                              int m0, int n0, float acc[2][8][4])
{
    const int t    = threadIdx.x;
    const int lane = t & 31;
    const int wid  = t >> 5;
    const int wm   = wid >> 1;
    const int wn   = wid & 1;

#pragma unroll
    for (int i = 0; i < 2; i++)
#pragma unroll
        for (int j = 0; j < 8; j++)
#pragma unroll
            for (int e = 0; e < 4; e++) acc[i][j][e] = 0.f;

    const int g  = lane >> 3;
    const int l8 = lane & 7;
    const int a_row = l8 + ((g & 1) << 3);
    const int a_col = (g >> 1) << 3;
    const int b_row = l8 + ((g >> 1) << 3);
    const int b_col = (g & 1) << 3;

    gemm_load_chunk(sm, 0, A, B, m0, n0, 0, t);
    CP_COMMIT();

    for (int ic = 0; ic < NCHUNKS; ic++) {
        const int buf = ic & 1;
        if (ic + 1 < NCHUNKS) {
            gemm_load_chunk(sm, buf ^ 1, A, B, m0, n0, (ic + 1) * KCHUNK, t);
            CP_COMMIT();
            CP_WAIT1();
        } else {
            CP_WAIT0();
        }
        __syncthreads();

#pragma unroll
        for (int ks = 0; ks < 2; ks++) {
            const int k0 = ks * 16;
            uint32_t af[2][4];
#pragma unroll
            for (int mi = 0; mi < 2; mi++)
                ldsm4(smem_u32(&sm->A[buf][wm * 32 + mi * 16 + a_row][k0 + a_col]),
                      af[mi]);
            uint32_t bf[4][4];
#pragma unroll
            for (int np = 0; np < 4; np++)
                ldsm4(smem_u32(&sm->B[buf][wn * 64 + np * 16 + b_row][k0 + b_col]),
                      bf[np]);
#pragma unroll
            for (int mi = 0; mi < 2; mi++)
#pragma unroll
                for (int np = 0; np < 4; np++) {
                    mma16816(acc[mi][2 * np],     af[mi], bf[np][0], bf[np][1]);
                    mma16816(acc[mi][2 * np + 1], af[mi], bf[np][2], bf[np][3]);
                }
        }
        __syncthreads();
    }
}

// -------------------- GEMM 1: QKV + split epilogue to planes -----------------
__global__ __launch_bounds__(256, 2)
void gemm_qkv_tc(const float* __restrict__ bias)
{
    __shared__ GemmSmem sm;
    const int m0 = blockIdx.y * 128, n0 = blockIdx.x * 128;

    float acc[2][8][4];
    gemm_mainloop(&sm, g_xs, g_wk, m0, n0, acc);

    const int t = threadIdx.x, lane = t & 31, wid = t >> 5;
    const int wm = wid >> 1, wn = wid & 1;

#pragma unroll
    for (int mi = 0; mi < 2; mi++) {
        const int r0 = m0 + wm * 32 + mi * 16 + (lane >> 2);
#pragma unroll
        for (int nf = 0; nf < 8; nf++) {
            const int c   = n0 + wn * 64 + nf * 8 + (lane & 3) * 2;
            const int h   = c / 192;
            const int rr  = c % 192;
            const int sel = rr >> 6;       // 0=k, 1=q, 2=v
            const int o   = rr & 63;
            const float scale = (sel == 1) ? 0.125f : 1.0f;
            __nv_bfloat16 *ph = (sel == 0) ? g_kh : (sel == 1) ? g_qh : g_vh;
            __nv_bfloat16 *pl = (sel == 0) ? g_kl : (sel == 1) ? g_ql : g_vl;
            const float bx = bias[c], by = bias[c + 1];
#pragma unroll
            for (int rh = 0; rh < 2; rh++) {
                const int m  = r0 + rh * 8;
                const int bb = m >> 11, n = m & 2047;
                const size_t i0 = (((size_t)(bb * NHEAD + h) * SEQ) + n) * HDIM + o;
                split_store(ph, pl, i0,
                            (acc[mi][nf][2 * rh + 0] + bx) * scale,
                            (acc[mi][nf][2 * rh + 1] + by) * scale);
            }
        }
    }
}

// ---------------------------- GEMM 2: projection -----------------------------
__global__ __launch_bounds__(256, 2)
void gemm_proj_tc(const float* __restrict__ bias, float* __restrict__ out)
{
    __shared__ GemmSmem sm;
    const int m0 = blockIdx.y * 128, n0 = blockIdx.x * 128;

    float acc[2][8][4];
    gemm_mainloop(&sm, g_sas, g_wp, m0, n0, acc);

    const int t = threadIdx.x, lane = t & 31, wid = t >> 5;
    const int wm = wid >> 1, wn = wid & 1;

#pragma unroll
    for (int mi = 0; mi < 2; mi++) {
        const int r0 = m0 + wm * 32 + mi * 16 + (lane >> 2);
#pragma unroll
        for (int nf = 0; nf < 8; nf++) {
            const int c = n0 + wn * 64 + nf * 8 + (lane & 3) * 2;
            const float bx = bias[c], by = bias[c + 1];
#pragma unroll
            for (int rh = 0; rh < 2; rh++) {
                const int m = r0 + rh * 8;
                float2 v;
                v.x = acc[mi][nf][2 * rh + 0] + bx;
                v.y = acc[mi][nf][2 * rh + 1] + by;
                *(float2*)&out[(size_t)m * DMODEL + c] = v;
            }
        }
    }
}

// ---------------------------- conversion kernel -----------------------------
__global__ __launch_bounds__(256)
void convert_split_kernel(const float* __restrict__ src, int out_sel, int pattern)
{
    __nv_bfloat16* out = (out_sel == 0) ? g_xs
                       : (out_sel == 1) ? g_wk : g_wp;

    const size_t gid = (size_t)blockIdx.x * 256 + threadIdx.x;   // one float4
    const size_t r = gid / 192;
    const int    c = (int)(gid % 192) * 4;
    float4 x = *(const float4*)&src[r * 768 + c];

    union BF4 { __nv_bfloat16 b[4]; uint2 u; };
    BF4 hi, lo;
    float xv[4] = {x.x, x.y, x.z, x.w};
#pragma unroll
    for (int i = 0; i < 4; i++) {
        hi.b[i] = __float2bfloat16(xv[i]);
        lo.b[i] = __float2bfloat16(xv[i] - __bfloat162float(hi.b[i]));
    }
    __nv_bfloat16* row = out + r * K2;
    *(uint2*)(row + c) = hi.u;
    if (pattern == 0) {
        *(uint2*)(row + 768  + c) = hi.u;
        *(uint2*)(row + 1536 + c) = lo.u;
    } else {
        *(uint2*)(row + 768  + c) = lo.u;
        *(uint2*)(row + 1536 + c) = hi.u;
    }
}

// =============================================================================
// Tensor-core causal flash attention.
// 256 threads (8 warps x m16 query rows), 64-key chunks, cp.async 2-stage.
// Attention smem pitch = 72 bf16 (144B/row): rows are HDIM=64 wide + 8 pad.
// 144 mod 128 = 16 -> ldmatrix 8-row groups hit 8 distinct 16B banks groups.
// Layout (bf16 elements):
//   Qh[128][72] @ 0        (9216)
//   Ql[128][72] @ 9216     (9216)
//   stages: 2 x { Kh,Kl,Vh,Vl [64][72] } @ 18432, plane stride 4608,
//           stage stride 18432.
// Total = 55296 elements = 110592 bytes.
// =============================================================================
#define VPITCH 72
#define AQH 0
#define AQL 9216
#define ACH 18432
#define PLSTRIDE 4608
#define STSTRIDE 18432
#define ATTN_SMEM_BYTES (55296 * 2)

__global__ __launch_bounds__(256)
void attn_tc()
{
    extern __shared__ __nv_bfloat16 sm[];
    const int bh = blockIdx.y;
    const int q0 = blockIdx.x * 128;
    const int t = threadIdx.x, lane = t & 31, wid = t >> 5;
    const int nch = (q0 >> 6) + 2;

    const size_t bhoff = (size_t)bh * SEQ * HDIM;
    const __nv_bfloat16 *Qh = g_qh + bhoff, *Ql = g_ql + bhoff;
    const __nv_bfloat16 *Kh = g_kh + bhoff, *Kl = g_kl + bhoff;
    const __nv_bfloat16 *Vh = g_vh + bhoff, *Vl = g_vl + bhoff;

    // ---- stage Q (both planes) + first K/V chunk via cp.async ----
#pragma unroll
    for (int i = 0; i < 8; i++) {
        const int idx = t + i * 256;          // 2048 groups: plane = idx>>10
        const int plane = idx >> 10;
        const int w = idx & 1023;
        const int r = w >> 3, c = (w & 7) * 8;
        const __nv_bfloat16* src = (plane ? Ql : Qh) + (size_t)(q0 + r) * HDIM + c;
        cp16(smem_u32(&sm[(plane ? AQL : AQH) + r * VPITCH + c]), src);
    }
    {
        // chunk 0 into stage 0
#pragma unroll
        for (int i = 0; i < 8; i++) {
            const int idx = t + i * 256;      // 2048 groups: plane = idx>>9
            const int plane = idx >> 9;
            const int w = idx & 511;
            const int r = w >> 3, c = (w & 7) * 8;
            const __nv_bfloat16* src =
                ((plane == 0) ? Kh : (plane == 1) ? Kl : (plane == 2) ? Vh : Vl)
                + (size_t)r * HDIM + c;
            cp16(smem_u32(&sm[ACH + plane * PLSTRIDE + r * VPITCH + c]), src);
        }
    }
    CP_COMMIT();

    float O[8][4];
#pragma unroll
    for (int nt = 0; nt < 8; nt++)
#pragma unroll
        for (int e = 0; e < 4; e++) O[nt][e] = 0.f;
    float mrun[2] = {-1e30f, -1e30f};
    float lrun[2] = {0.f, 0.f};

    const int g  = lane >> 3;
    const int l8 = lane & 7;
    const int a_row = l8 + ((g & 1) << 3);
    const int a_col = (g >> 1) << 3;
    const int b_row = l8 + ((g >> 1) << 3);
    const int b_col = (g & 1) << 3;
    const int v_row = l8 + ((g & 1) << 3);   // key offset within ktile16
    const int v_col = (g >> 1) << 3;         // hd offset within 16-wide tile

    for (int ic = 0; ic < nch; ic++) {
        const int s0 = ic * 64;
        const int buf = ic & 1;
        if (ic + 1 < nch) {
            const int s1 = (ic + 1) * 64;
            const int nb = ACH + (buf ^ 1) * STSTRIDE;
#pragma unroll
            for (int i = 0; i < 8; i++) {
                const int idx = t + i * 256;
                const int plane = idx >> 9;
                const int w = idx & 511;
                const int r = w >> 3, c = (w & 7) * 8;
                const __nv_bfloat16* src =
                    ((plane == 0) ? Kh : (plane == 1) ? Kl : (plane == 2) ? Vh : Vl)
                    + (size_t)(s1 + r) * HDIM + c;
                cp16(smem_u32(&sm[nb + plane * PLSTRIDE + r * VPITCH + c]), src);
            }
            CP_COMMIT();
            CP_WAIT1();
        } else {
            CP_WAIT0();
        }
        __syncthreads();

        const int kbase = ACH + buf * STSTRIDE;
        const int vbase = kbase + 2 * PLSTRIDE;

        // ---- S = Qh*Kh + Qh*Kl + Ql*Kh ----
        float S[8][4];
#pragma unroll
        for (int nt = 0; nt < 8; nt++)
#pragma unroll
            for (int e = 0; e < 4; e++) S[nt][e] = 0.f;

#pragma unroll
        for (int kt = 0; kt < 4; kt++) {
            uint32_t ah[4], al[4];
            ldsm4(smem_u32(&sm[AQH + (wid * 16 + a_row) * VPITCH + kt * 16 + a_col]), ah);
            ldsm4(smem_u32(&sm[AQL + (wid * 16 + a_row) * VPITCH + kt * 16 + a_col]), al);
#pragma unroll
            for (int np = 0; np < 4; np++) {
                uint32_t kh4[4], kl4[4];
                ldsm4(smem_u32(&sm[kbase + (np * 16 + b_row) * VPITCH + kt * 16 + b_col]), kh4);
                ldsm4(smem_u32(&sm[kbase + PLSTRIDE + (np * 16 + b_row) * VPITCH + kt * 16 + b_col]), kl4);
                mma16816(S[2 * np],     ah, kh4[0], kh4[1]);
                mma16816(S[2 * np + 1], ah, kh4[2], kh4[3]);
                mma16816(S[2 * np],     ah, kl4[0], kl4[1]);
                mma16816(S[2 * np + 1], ah, kl4[2], kl4[3]);
                mma16816(S[2 * np],     al, kh4[0], kh4[1]);
                mma16816(S[2 * np + 1], al, kh4[2], kh4[3]);
            }
        }

        // ---- causal mask ----
        const int rowbase = q0 + wid * 16 + (lane >> 2);
        if (s0 + 63 > q0 + wid * 16) {
#pragma unroll
            for (int nt = 0; nt < 8; nt++)
#pragma unroll
                for (int e = 0; e < 4; e++) {
                    const int row = rowbase + ((e >> 1) << 3);
                    const int col = s0 + nt * 8 + ((lane & 3) << 1) + (e & 1);
                    if (col > row) S[nt][e] = -1e30f;
                }
        }

        // ---- online softmax ----
        float rmax[2] = {-1e30f, -1e30f};
#pragma unroll
        for (int nt = 0; nt < 8; nt++) {
            rmax[0] = fmaxf(rmax[0], fmaxf(S[nt][0], S[nt][1]));
            rmax[1] = fmaxf(rmax[1], fmaxf(S[nt][2], S[nt][3]));
        }
        float alpha[2];
#pragma unroll
        for (int r = 0; r < 2; r++) {
            rmax[r] = fmaxf(rmax[r], __shfl_xor_sync(0xffffffffu, rmax[r], 1));
            rmax[r] = fmaxf(rmax[r], __shfl_xor_sync(0xffffffffu, rmax[r], 2));
            const float mn = fmaxf(mrun[r], rmax[r]);
            alpha[r] = __expf(mrun[r] - mn);
            mrun[r] = mn;
        }
        float lsum[2] = {0.f, 0.f};
#pragma unroll
        for (int nt = 0; nt < 8; nt++)
#pragma unroll
            for (int e = 0; e < 4; e++) {
                const float p = __expf(S[nt][e] - mrun[e >> 1]);
                S[nt][e] = p;
                lsum[e >> 1] += p;
            }
#pragma unroll
        for (int r = 0; r < 2; r++) {
            lsum[r] += __shfl_xor_sync(0xffffffffu, lsum[r], 1);
            lsum[r] += __shfl_xor_sync(0xffffffffu, lsum[r], 2);
            lrun[r] = lrun[r] * alpha[r] + lsum[r];
        }
#pragma unroll
        for (int nt = 0; nt < 8; nt++)
#pragma unroll
            for (int e = 0; e < 4; e++) O[nt][e] *= alpha[e >> 1];

        // ---- PV: O += Ph*Vh + Ph*Vl + Pl*Vh ----
#pragma unroll
        for (int kt = 0; kt < 4; kt++) {
            uint32_t ph[4], pl[4];
            {
                const float* s0p = S[2 * kt];
                const float* s1p = S[2 * kt + 1];
                float rh[8], rl[8];
#pragma unroll
                for (int e = 0; e < 4; e++) {
                    float v0 = s0p[e], v1 = s1p[e];
                    __nv_bfloat16 h0 = __float2bfloat16(v0);
                    __nv_bfloat16 h1 = __float2bfloat16(v1);
                    rh[e]     = __bfloat162float(h0);
                    rh[4 + e] = __bfloat162float(h1);
                    rl[e]     = v0 - rh[e];
                    rl[4 + e] = v1 - rh[4 + e];
                }
                ph[0] = packbf2(rh[0], rh[1]);
                ph[1] = packbf2(rh[2], rh[3]);
                ph[2] = packbf2(rh[4], rh[5]);
                ph[3] = packbf2(rh[6], rh[7]);
                pl[0] = packbf2(rl[0], rl[1]);
                pl[1] = packbf2(rl[2], rl[3]);
                pl[2] = packbf2(rl[4], rl[5]);
                pl[3] = packbf2(rl[6], rl[7]);
            }
#pragma unroll
            for (int hp = 0; hp < 4; hp++) {
                uint32_t vh4[4], vl4[4];
                ldsm4t(smem_u32(&sm[vbase + (kt * 16 + v_row) * VPITCH + hp * 16 + v_col]), vh4);
                ldsm4t(smem_u32(&sm[vbase + PLSTRIDE + (kt * 16 + v_row) * VPITCH + hp * 16 + v_col]), vl4);
                mma16816(O[2 * hp],     ph, vh4[0], vh4[1]);
                mma16816(O[2 * hp + 1], ph, vh4[2], vh4[3]);
                mma16816(O[2 * hp],     ph, vl4[0], vl4[1]);
                mma16816(O[2 * hp + 1], ph, vl4[2], vl4[3]);
                mma16816(O[2 * hp],     pl, vh4[0], vh4[1]);
                mma16816(O[2 * hp + 1], pl, vh4[2], vh4[3]);
            }
        }
        __syncthreads();
    }

    // ---- epilogue: normalize, split, write g_sas [hi | hi | lo] ----
    const int b = bh / NHEAD;
    const int h = bh % NHEAD;
#pragma unroll
    for (int r = 0; r < 2; r++) {
        const float inv = 1.f / lrun[r];
        const int n = q0 + wid * 16 + (lane >> 2) + r * 8;
        __nv_bfloat16* rowp = g_sas + (size_t)(b * SEQ + n) * K2;
#pragma unroll
        for (int nt = 0; nt < 8; nt++) {
            const int c = h * HDIM + nt * 8 + ((lane & 3) << 1);
            const float f0 = O[nt][2 * r + 0] * inv;
            const float f1 = O[nt][2 * r + 1] * inv;
            __nv_bfloat16 h0 = __float2bfloat16(f0), h1 = __float2bfloat16(f1);
            __nv_bfloat162 hv; hv.x = h0; hv.y = h1;
            __nv_bfloat162 lv;
            lv.x = __float2bfloat16(f0 - __bfloat162float(h0));
            lv.y = __float2bfloat16(f1 - __bfloat162float(h1));
            *(__nv_bfloat162*)&rowp[c]        = hv;
            *(__nv_bfloat162*)&rowp[768 + c]  = hv;
            *(__nv_bfloat162*)&rowp[1536 + c] = lv;
        }
    }
}

// ---------------------------------------------------------------------------
extern "C" void kernel_launch(void* const* d_in, const int* in_sizes, int n_in,
                              void* d_out, int out_size)
{
    const float* x      = (const float*)d_in[0];  // [B, N, D]
    const float* W_kqv  = (const float*)d_in[1];  // [H, 3*HD, D]
    const float* b_kqv  = (const float*)d_in[2];  // [H, 3*HD]
    const float* W_proj = (const float*)d_in[3];  // [D, D]
    const float* b_proj = (const float*)d_in[4];  // [D]
    float* out = (float*)d_out;

    (void)in_sizes; (void)n_in; (void)out_size;

    cudaFuncSetAttribute(attn_tc, cudaFuncAttributeMaxDynamicSharedMemorySize,
                         ATTN_SMEM_BYTES);

    // split conversions (inputs only; SA split is fused into attention)
    convert_split_kernel<<<3072, 256>>>(x,      0, 0);  // X    -> g_xs  [hi|hi|lo]
    convert_split_kernel<<<1728, 256>>>(W_kqv,  1, 1);  // Wkqv -> g_wk  [hi|lo|hi]
    convert_split_kernel<<<576,  256>>>(W_proj, 2, 1);  // Wproj-> g_wp  [hi|lo|hi]

    // QKV projection (HMMA) with fused bf16 hi/lo split epilogue
    {
        dim3 grid(QKV_COLS / 128, M_ROWS / 128);   // 18 x 32
        gemm_qkv_tc<<<grid, 256>>>(b_kqv);
    }
    // tensor-core causal flash attention, writes g_sas directly
    {
        dim3 grid(SEQ / 128, BATCH * NHEAD);       // 16 x 24
        attn_tc<<<grid, 256, ATTN_SMEM_BYTES>>>();
    }
    // output projection
    {
        dim3 grid(DMODEL / 128, M_ROWS / 128);     // 6 x 32
        gemm_proj_tc<<<grid, 256>>>(b_proj, out);
    }
}

// round 7
// speedup vs baseline: 3.4431x; 1.0447x over previous
#include <cuda_runtime.h>
#include <cuda_bf16.h>
#include <math.h>
#include <stdint.h>

#define BATCH 2
#define SEQ   2048
#define DMODEL 768
#define NHEAD 12
#define HDIM  64
#define M_ROWS (BATCH * SEQ)          // 4096
#define QKV_COLS (NHEAD * 3 * HDIM)   // 2304
#define K2 2304                       // expanded K' = 3*768
#define KCHUNK 32
#define NCHUNKS (K2 / KCHUNK)         // 72
#define APITCH 40                     // GEMM smem pitch (rows 32 wide + 8 pad)

// Q pre-scale: 1/sqrt(64) * log2(e)  (softmax computed in exp2 domain)
#define QSCALE 0.1803368801111244f

// ------------------------------ device scratch ------------------------------
__device__ __nv_bfloat16 g_xs [(size_t)M_ROWS   * K2]; // X  split  [hi|hi|lo]
__device__ __nv_bfloat16 g_wk [(size_t)QKV_COLS * K2]; // Wkqv split[hi|lo|hi]
__device__ __nv_bfloat16 g_wp [(size_t)DMODEL   * K2]; // Wproj split[hi|lo|hi]
__device__ __nv_bfloat16 g_sas[(size_t)M_ROWS   * K2]; // SA split  [hi|hi|lo]

#define QKV_ELEMS ((size_t)BATCH * NHEAD * SEQ * HDIM)
__device__ __nv_bfloat16 g_qh[QKV_ELEMS], g_ql[QKV_ELEMS];
__device__ __nv_bfloat16 g_kh[QKV_ELEMS], g_kl[QKV_ELEMS];
__device__ __nv_bfloat16 g_vh[QKV_ELEMS], g_vl[QKV_ELEMS];

// ------------------------------ PTX helpers ---------------------------------
__device__ __forceinline__ uint32_t smem_u32(const void* p) {
    uint32_t a;
    asm("{ .reg .u64 t; cvta.to.shared.u64 t, %1; cvt.u32.u64 %0, t; }"
        : "=r"(a) : "l"(p));
    return a;
}
__device__ __forceinline__ void cp16(uint32_t dst, const void* src) {
    asm volatile("cp.async.cg.shared.global [%0], [%1], 16;"
                 :: "r"(dst), "l"(src) : "memory");
}
#define CP_COMMIT() asm volatile("cp.async.commit_group;" ::: "memory")
#define CP_WAIT2()  asm volatile("cp.async.wait_group 2;" ::: "memory")
#define CP_WAIT0()  asm volatile("cp.async.wait_group 0;" ::: "memory")

__device__ __forceinline__ void ldsm4(uint32_t addr, uint32_t r[4]) {
    asm volatile("ldmatrix.sync.aligned.m8n8.x4.shared.b16 {%0,%1,%2,%3}, [%4];"
                 : "=r"(r[0]), "=r"(r[1]), "=r"(r[2]), "=r"(r[3]) : "r"(addr));
}
__device__ __forceinline__ void ldsm4t(uint32_t addr, uint32_t r[4]) {
    asm volatile("ldmatrix.sync.aligned.m8n8.x4.trans.shared.b16 {%0,%1,%2,%3}, [%4];"
                 : "=r"(r[0]), "=r"(r[1]), "=r"(r[2]), "=r"(r[3]) : "r"(addr));
}
__device__ __forceinline__ void mma16816(float d[4], const uint32_t a[4],
                                         uint32_t b0, uint32_t b1) {
    asm volatile(
        "mma.sync.aligned.m16n8k16.row.col.f32.bf16.bf16.f32 "
        "{%0,%1,%2,%3}, {%4,%5,%6,%7}, {%8,%9}, {%0,%1,%2,%3};"
        : "+f"(d[0]), "+f"(d[1]), "+f"(d[2]), "+f"(d[3])
        : "r"(a[0]), "r"(a[1]), "r"(a[2]), "r"(a[3]), "r"(b0), "r"(b1));
}
__device__ __forceinline__ float ex2(float x) {
    float r;
    asm("ex2.approx.ftz.f32 %0, %1;" : "=f"(r) : "f"(x));
    return r;
}
// pack high halves of two fp32 into bf16x2 (a -> low, b -> high)
__device__ __forceinline__ uint32_t prmt_hi2(uint32_t a, uint32_t b) {
    uint32_t r;
    asm("prmt.b32 %0, %1, %2, 0x7632;" : "=r"(r) : "r"(a), "r"(b));
    return r;
}

// split-store helper (round-nearest hi/lo) for Q/K/V planes
__device__ __forceinline__ void split_store(__nv_bfloat16* ph, __nv_bfloat16* pl,
                                            size_t idx, float f0, float f1) {
    __nv_bfloat16 h0 = __float2bfloat16(f0), h1 = __float2bfloat16(f1);
    float r0 = f0 - __bfloat162float(h0), r1 = f1 - __bfloat162float(h1);
    __nv_bfloat162 hv; hv.x = h0; hv.y = h1;
    __nv_bfloat162 lv; lv.x = __float2bfloat16(r0); lv.y = __float2bfloat16(r1);
    *(__nv_bfloat162*)&ph[idx] = hv;
    *(__nv_bfloat162*)&pl[idx] = lv;
}

// =============================================================================
// HMMA GEMM core: 128x128 tile, 256 threads, K-chunk 32, 4-stage cp.async ring,
// ONE __syncthreads per iteration.
// Dynamic smem layout (bf16 elems): A stages 0..3 at s*5120, B at 20480+s*5120.
// =============================================================================
#define GEMM_SMEM_BYTES (8 * 5120 * 2)   // 81920

__device__ __forceinline__ void gemm_load_chunk(__nv_bfloat16* sm, int s,
                                                const __nv_bfloat16* __restrict__ A,
                                                const __nv_bfloat16* __restrict__ B,
                                                int m0, int n0, int k0, int t)
{
    __nv_bfloat16* As = sm + s * 5120;
    __nv_bfloat16* Bs = sm + 20480 + s * 5120;
#pragma unroll
    for (int i = 0; i < 2; i++) {
        const int idx = i * 256 + t;
        const int row = idx >> 2;
        const int c   = (idx & 3) * 8;
        cp16(smem_u32(&As[row * APITCH + c]), &A[(size_t)(m0 + row) * K2 + k0 + c]);
        cp16(smem_u32(&Bs[row * APITCH + c]), &B[(size_t)(n0 + row) * K2 + k0 + c]);
    }
}

__device__ __forceinline__ void gemm_mainloop(__nv_bfloat16* sm,
                                              const __nv_bfloat16* __restrict__ A,
                                              const __nv_bfloat16* __restrict__ B,
                                              int m0, int n0, float acc[2][8][4])
{
    const int t    = threadIdx.x;
    const int lane = t & 31;
    const int wid  = t >> 5;
    const int wm   = wid >> 1;
    const int wn   = wid & 1;

#pragma unroll
    for (int i = 0; i < 2; i++)
#pragma unroll
        for (int j = 0; j < 8; j++)
#pragma unroll
            for (int e = 0; e < 4; e++) acc[i][j][e] = 0.f;

    const int g  = lane >> 3;
    const int l8 = lane & 7;
    const int a_row = l8 + ((g & 1) << 3);
    const int a_col = (g >> 1) << 3;
    const int b_row = l8 + ((g >> 1) << 3);
    const int b_col = (g & 1) << 3;

    // prologue: stages 0..2 in flight
#pragma unroll
    for (int s = 0; s < 3; s++) {
        gemm_load_chunk(sm, s, A, B, m0, n0, s * KCHUNK, t);
        CP_COMMIT();
    }

    for (int ic = 0; ic < NCHUNKS; ic++) {
        CP_WAIT2();                 // chunk ic resident
        __syncthreads();            // all warps done with stage (ic+3)&3 reads
        if (ic + 3 < NCHUNKS)
            gemm_load_chunk(sm, (ic + 3) & 3, A, B, m0, n0, (ic + 3) * KCHUNK, t);
        CP_COMMIT();                // always commit (group accounting)

        const int buf = ic & 3;
        __nv_bfloat16* As = sm + buf * 5120;
        __nv_bfloat16* Bs = sm + 20480 + buf * 5120;
#pragma unroll
        for (int ks = 0; ks < 2; ks++) {
            const int k0 = ks * 16;
            uint32_t af[2][4];
#pragma unroll
            for (int mi = 0; mi < 2; mi++)
                ldsm4(smem_u32(&As[(wm * 32 + mi * 16 + a_row) * APITCH + k0 + a_col]),
                      af[mi]);
            uint32_t bfm[4][4];
#pragma unroll
            for (int np = 0; np < 4; np++)
                ldsm4(smem_u32(&Bs[(wn * 64 + np * 16 + b_row) * APITCH + k0 + b_col]),
                      bfm[np]);
#pragma unroll
            for (int mi = 0; mi < 2; mi++)
#pragma unroll
                for (int np = 0; np < 4; np++) {
                    mma16816(acc[mi][2 * np],     af[mi], bfm[np][0], bfm[np][1]);
                    mma16816(acc[mi][2 * np + 1], af[mi], bfm[np][2], bfm[np][3]);
                }
        }
    }
}

// -------------------- GEMM 1: QKV + split epilogue to planes -----------------
__global__ __launch_bounds__(256, 2)
void gemm_qkv_tc(const float* __restrict__ bias)
{
    extern __shared__ __nv_bfloat16 gsm[];
    const int m0 = blockIdx.y * 128, n0 = blockIdx.x * 128;

    float acc[2][8][4];
    gemm_mainloop(gsm, g_xs, g_wk, m0, n0, acc);

    const int t = threadIdx.x, lane = t & 31, wid = t >> 5;
    const int wm = wid >> 1, wn = wid & 1;

#pragma unroll
    for (int mi = 0; mi < 2; mi++) {
        const int r0 = m0 + wm * 32 + mi * 16 + (lane >> 2);
#pragma unroll
        for (int nf = 0; nf < 8; nf++) {
            const int c   = n0 + wn * 64 + nf * 8 + (lane & 3) * 2;
            const int h   = c / 192;
            const int rr  = c % 192;
            const int sel = rr >> 6;       // 0=k, 1=q, 2=v
            const int o   = rr & 63;
            const float scale = (sel == 1) ? QSCALE : 1.0f;
            __nv_bfloat16 *ph = (sel == 0) ? g_kh : (sel == 1) ? g_qh : g_vh;
            __nv_bfloat16 *pl = (sel == 0) ? g_kl : (sel == 1) ? g_ql : g_vl;
            const float bx = bias[c], by = bias[c + 1];
#pragma unroll
            for (int rh = 0; rh < 2; rh++) {
                const int m  = r0 + rh * 8;
                const int bb = m >> 11, n = m & 2047;
                const size_t i0 = (((size_t)(bb * NHEAD + h) * SEQ) + n) * HDIM + o;
                split_store(ph, pl, i0,
                            (acc[mi][nf][2 * rh + 0] + bx) * scale,
                            (acc[mi][nf][2 * rh + 1] + by) * scale);
            }
        }
    }
}

// ---------------------------- GEMM 2: projection -----------------------------
__global__ __launch_bounds__(256, 2)
void gemm_proj_tc(const float* __restrict__ bias, float* __restrict__ out)
{
    extern __shared__ __nv_bfloat16 gsm[];
    const int m0 = blockIdx.y * 128, n0 = blockIdx.x * 128;

    float acc[2][8][4];
    gemm_mainloop(gsm, g_sas, g_wp, m0, n0, acc);

    const int t = threadIdx.x, lane = t & 31, wid = t >> 5;
    const int wm = wid >> 1, wn = wid & 1;

#pragma unroll
    for (int mi = 0; mi < 2; mi++) {
        const int r0 = m0 + wm * 32 + mi * 16 + (lane >> 2);
#pragma unroll
        for (int nf = 0; nf < 8; nf++) {
            const int c = n0 + wn * 64 + nf * 8 + (lane & 3) * 2;
            const float bx = bias[c], by = bias[c + 1];
#pragma unroll
            for (int rh = 0; rh < 2; rh++) {
                const int m = r0 + rh * 8;
                float2 v;
                v.x = acc[mi][nf][2 * rh + 0] + bx;
                v.y = acc[mi][nf][2 * rh + 1] + by;
                *(float2*)&out[(size_t)m * DMODEL + c] = v;
            }
        }
    }
}

// --------------------- fused conversion kernel (X, Wkqv, Wproj) --------------
__global__ __launch_bounds__(256)
void convert_all(const float* __restrict__ x,
                 const float* __restrict__ wk,
                 const float* __restrict__ wp)
{
    const int b = blockIdx.x;
    const float* src;
    __nv_bfloat16* out;
    int pattern;
    size_t gid;
    if (b < 3072)      { src = x;  out = g_xs; pattern = 0; gid = (size_t)b * 256; }
    else if (b < 4800) { src = wk; out = g_wk; pattern = 1; gid = (size_t)(b - 3072) * 256; }
    else               { src = wp; out = g_wp; pattern = 1; gid = (size_t)(b - 4800) * 256; }
    gid += threadIdx.x;

    const size_t r = gid / 192;
    const int    c = (int)(gid % 192) * 4;
    float4 xv4 = *(const float4*)&src[r * 768 + c];

    union BF4 { __nv_bfloat16 bb[4]; uint2 u; };
    BF4 hi, lo;
    float xv[4] = {xv4.x, xv4.y, xv4.z, xv4.w};
#pragma unroll
    for (int i = 0; i < 4; i++) {
        hi.bb[i] = __float2bfloat16(xv[i]);
        lo.bb[i] = __float2bfloat16(xv[i] - __bfloat162float(hi.bb[i]));
    }
    __nv_bfloat16* row = out + r * K2;
    *(uint2*)(row + c) = hi.u;
    if (pattern == 0) {
        *(uint2*)(row + 768  + c) = hi.u;
        *(uint2*)(row + 1536 + c) = lo.u;
    } else {
        *(uint2*)(row + 768  + c) = lo.u;
        *(uint2*)(row + 1536 + c) = hi.u;
    }
}

// =============================================================================
// Tensor-core causal flash attention (exp2-domain softmax).
// 256 threads (8 warps x m16 rows), 64-key chunks, cp.async, 1 sync/chunk.
// Pitch 72 bf16 (144B). Layout: Qh@0, Ql@9216, stages @18432 (plane 4608,
// stage 18432). Total 110592 B.
// =============================================================================
#define VPITCH 72
#define AQH 0
#define AQL 9216
#define ACH 18432
#define PLSTRIDE 4608
#define STSTRIDE 18432
#define ATTN_SMEM_BYTES (55296 * 2)

__global__ __launch_bounds__(256)
void attn_tc()
{
    extern __shared__ __nv_bfloat16 sm[];
    const int bh = blockIdx.y;
    const int q0 = blockIdx.x * 128;
    const int t = threadIdx.x, lane = t & 31, wid = t >> 5;
    const int nch = (q0 >> 6) + 2;

    const size_t bhoff = (size_t)bh * SEQ * HDIM;
    const __nv_bfloat16 *Qh = g_qh + bhoff, *Ql = g_ql + bhoff;
    const __nv_bfloat16 *Kh = g_kh + bhoff, *Kl = g_kl + bhoff;
    const __nv_bfloat16 *Vh = g_vh + bhoff, *Vl = g_vl + bhoff;

    // ---- prologue: Q (both planes) + chunk 0, single group ----
#pragma unroll
    for (int i = 0; i < 8; i++) {
        const int idx = t + i * 256;
        const int plane = idx >> 10;
        const int w = idx & 1023;
        const int r = w >> 3, c = (w & 7) * 8;
        const __nv_bfloat16* src = (plane ? Ql : Qh) + (size_t)(q0 + r) * HDIM + c;
        cp16(smem_u32(&sm[(plane ? AQL : AQH) + r * VPITCH + c]), src);
    }
#pragma unroll
    for (int i = 0; i < 8; i++) {
        const int idx = t + i * 256;
        const int plane = idx >> 9;
        const int w = idx & 511;
        const int r = w >> 3, c = (w & 7) * 8;
        const __nv_bfloat16* src =
            ((plane == 0) ? Kh : (plane == 1) ? Kl : (plane == 2) ? Vh : Vl)
            + (size_t)r * HDIM + c;
        cp16(smem_u32(&sm[ACH + plane * PLSTRIDE + r * VPITCH + c]), src);
    }
    CP_COMMIT();
    CP_WAIT0();
    __syncthreads();

    float O[8][4];
#pragma unroll
    for (int nt = 0; nt < 8; nt++)
#pragma unroll
        for (int e = 0; e < 4; e++) O[nt][e] = 0.f;
    float mrun[2] = {-1e30f, -1e30f};
    float lrun[2] = {0.f, 0.f};

    const int g  = lane >> 3;
    const int l8 = lane & 7;
    const int a_row = l8 + ((g & 1) << 3);
    const int a_col = (g >> 1) << 3;
    const int b_row = l8 + ((g >> 1) << 3);
    const int b_col = (g & 1) << 3;
    const int v_row = l8 + ((g & 1) << 3);
    const int v_col = (g >> 1) << 3;

    for (int ic = 0; ic < nch; ic++) {
        const int buf = ic & 1;
        if (ic > 0) {
            CP_WAIT0();             // chunk ic resident (loaded during compute ic-1)
            __syncthreads();        // all warps done reading stage buf (iter ic-2)
        }
        if (ic + 1 < nch) {
            const int s1 = (ic + 1) * 64;
            const int nb = ACH + (buf ^ 1) * STSTRIDE;
#pragma unroll
            for (int i = 0; i < 8; i++) {
                const int idx = t + i * 256;
                const int plane = idx >> 9;
                const int w = idx & 511;
                const int r = w >> 3, c = (w & 7) * 8;
                const __nv_bfloat16* src =
                    ((plane == 0) ? Kh : (plane == 1) ? Kl : (plane == 2) ? Vh : Vl)
                    + (size_t)(s1 + r) * HDIM + c;
                cp16(smem_u32(&sm[nb + plane * PLSTRIDE + r * VPITCH + c]), src);
            }
        }
        CP_COMMIT();

        const int s0 = ic * 64;
        const int kbase = ACH + buf * STSTRIDE;
        const int vbase = kbase + 2 * PLSTRIDE;

        // ---- S = Qh*Kh + Qh*Kl + Ql*Kh  (log2-domain scores) ----
        float S[8][4];
#pragma unroll
        for (int nt = 0; nt < 8; nt++)
#pragma unroll
            for (int e = 0; e < 4; e++) S[nt][e] = 0.f;

#pragma unroll
        for (int kt = 0; kt < 4; kt++) {
            uint32_t ah[4], al[4];
            ldsm4(smem_u32(&sm[AQH + (wid * 16 + a_row) * VPITCH + kt * 16 + a_col]), ah);
            ldsm4(smem_u32(&sm[AQL + (wid * 16 + a_row) * VPITCH + kt * 16 + a_col]), al);
#pragma unroll
            for (int np = 0; np < 4; np++) {
                uint32_t kh4[4], kl4[4];
                ldsm4(smem_u32(&sm[kbase + (np * 16 + b_row) * VPITCH + kt * 16 + b_col]), kh4);
                ldsm4(smem_u32(&sm[kbase + PLSTRIDE + (np * 16 + b_row) * VPITCH + kt * 16 + b_col]), kl4);
                mma16816(S[2 * np],     ah, kh4[0], kh4[1]);
                mma16816(S[2 * np + 1], ah, kh4[2], kh4[3]);
                mma16816(S[2 * np],     ah, kl4[0], kl4[1]);
                mma16816(S[2 * np + 1], ah, kl4[2], kl4[3]);
                mma16816(S[2 * np],     al, kh4[0], kh4[1]);
                mma16816(S[2 * np + 1], al, kh4[2], kh4[3]);
            }
        }

        // ---- causal mask ----
        const int rowbase = q0 + wid * 16 + (lane >> 2);
        if (s0 + 63 > q0 + wid * 16) {
#pragma unroll
            for (int nt = 0; nt < 8; nt++)
#pragma unroll
                for (int e = 0; e < 4; e++) {
                    const int row = rowbase + ((e >> 1) << 3);
                    const int col = s0 + nt * 8 + ((lane & 3) << 1) + (e & 1);
                    if (col > row) S[nt][e] = -1e30f;
                }
        }

        // ---- online softmax (base-2) ----
        float rmax[2] = {-1e30f, -1e30f};
#pragma unroll
        for (int nt = 0; nt < 8; nt++) {
            rmax[0] = fmaxf(rmax[0], fmaxf(S[nt][0], S[nt][1]));
            rmax[1] = fmaxf(rmax[1], fmaxf(S[nt][2], S[nt][3]));
        }
        float alpha[2];
#pragma unroll
        for (int r = 0; r < 2; r++) {
            rmax[r] = fmaxf(rmax[r], __shfl_xor_sync(0xffffffffu, rmax[r], 1));
            rmax[r] = fmaxf(rmax[r], __shfl_xor_sync(0xffffffffu, rmax[r], 2));
            const float mn = fmaxf(mrun[r], rmax[r]);
            alpha[r] = ex2(mrun[r] - mn);
            mrun[r] = mn;
        }
        float lsum[2] = {0.f, 0.f};
#pragma unroll
        for (int nt = 0; nt < 8; nt++)
#pragma unroll
            for (int e = 0; e < 4; e++) {
                const float p = ex2(S[nt][e] - mrun[e >> 1]);
                S[nt][e] = p;
                lsum[e >> 1] += p;
            }
#pragma unroll
        for (int r = 0; r < 2; r++) {
            lsum[r] += __shfl_xor_sync(0xffffffffu, lsum[r], 1);
            lsum[r] += __shfl_xor_sync(0xffffffffu, lsum[r], 2);
            lrun[r] = lrun[r] * alpha[r] + lsum[r];
        }
#pragma unroll
        for (int nt = 0; nt < 8; nt++)
#pragma unroll
            for (int e = 0; e < 4; e++) O[nt][e] *= alpha[e >> 1];

        // ---- PV: O += Ph*Vh + Ph*Vl + Pl*Vh (truncation split via AND/PRMT) --
#pragma unroll
        for (int kt = 0; kt < 4; kt++) {
            uint32_t ph[4], pl[4];
            {
                const float* sp0 = S[2 * kt];
                const float* sp1 = S[2 * kt + 1];
#pragma unroll
                for (int h2 = 0; h2 < 2; h2++) {
                    const float* sp = h2 ? sp1 : sp0;
#pragma unroll
                    for (int pp = 0; pp < 2; pp++) {
                        const float f0 = sp[2 * pp], f1 = sp[2 * pp + 1];
                        const uint32_t u0 = __float_as_uint(f0);
                        const uint32_t u1 = __float_as_uint(f1);
                        ph[2 * h2 + pp] = prmt_hi2(u0, u1);
                        const float l0 = f0 - __uint_as_float(u0 & 0xFFFF0000u);
                        const float l1 = f1 - __uint_as_float(u1 & 0xFFFF0000u);
                        pl[2 * h2 + pp] = prmt_hi2(__float_as_uint(l0),
                                                   __float_as_uint(l1));
                    }
                }
            }
#pragma unroll
            for (int hp = 0; hp < 4; hp++) {
                uint32_t vh4[4], vl4[4];
                ldsm4t(smem_u32(&sm[vbase + (kt * 16 + v_row) * VPITCH + hp * 16 + v_col]), vh4);
                ldsm4t(smem_u32(&sm[vbase + PLSTRIDE + (kt * 16 + v_row) * VPITCH + hp * 16 + v_col]), vl4);
                mma16816(O[2 * hp],     ph, vh4[0], vh4[1]);
                mma16816(O[2 * hp + 1], ph, vh4[2], vh4[3]);
                mma16816(O[2 * hp],     ph, vl4[0], vl4[1]);
                mma16816(O[2 * hp + 1], ph, vl4[2], vl4[3]);
                mma16816(O[2 * hp],     pl, vh4[0], vh4[1]);
                mma16816(O[2 * hp + 1], pl, vh4[2], vh4[3]);
            }
        }
    }

    // ---- epilogue: normalize, split, write g_sas [hi | hi | lo] ----
    const int b = bh / NHEAD;
    const int h = bh % NHEAD;
#pragma unroll
    for (int r = 0; r < 2; r++) {
        const float inv = 1.f / lrun[r];
        const int n = q0 + wid * 16 + (lane >> 2) + r * 8;
        __nv_bfloat16* rowp = g_sas + (size_t)(b * SEQ + n) * K2;
#pragma unroll
        for (int nt = 0; nt < 8; nt++) {
            const int c = h * HDIM + nt * 8 + ((lane & 3) << 1);
            const float f0 = O[nt][2 * r + 0] * inv;
            const float f1 = O[nt][2 * r + 1] * inv;
            __nv_bfloat16 h0 = __float2bfloat16(f0), h1 = __float2bfloat16(f1);
            __nv_bfloat162 hv; hv.x = h0; hv.y = h1;
            __nv_bfloat162 lv;
            lv.x = __float2bfloat16(f0 - __bfloat162float(h0));
            lv.y = __float2bfloat16(f1 - __bfloat162float(h1));
            *(__nv_bfloat162*)&rowp[c]        = hv;
            *(__nv_bfloat162*)&rowp[768 + c]  = hv;
            *(__nv_bfloat162*)&rowp[1536 + c] = lv;
        }
    }
}

// ---------------------------------------------------------------------------
extern "C" void kernel_launch(void* const* d_in, const int* in_sizes, int n_in,
                              void* d_out, int out_size)
{
    const float* x      = (const float*)d_in[0];  // [B, N, D]
    const float* W_kqv  = (const float*)d_in[1];  // [H, 3*HD, D]
    const float* b_kqv  = (const float*)d_in[2];  // [H, 3*HD]
    const float* W_proj = (const float*)d_in[3];  // [D, D]
    const float* b_proj = (const float*)d_in[4];  // [D]
    float* out = (float*)d_out;

    (void)in_sizes; (void)n_in; (void)out_size;

    cudaFuncSetAttribute(attn_tc, cudaFuncAttributeMaxDynamicSharedMemorySize,
                         ATTN_SMEM_BYTES);
    cudaFuncSetAttribute(gemm_qkv_tc, cudaFuncAttributeMaxDynamicSharedMemorySize,
                         GEMM_SMEM_BYTES);
    cudaFuncSetAttribute(gemm_proj_tc, cudaFuncAttributeMaxDynamicSharedMemorySize,
                         GEMM_SMEM_BYTES);

    // fused split conversions (X, Wkqv, Wproj)
    convert_all<<<5376, 256>>>(x, W_kqv, W_proj);

    // QKV projection (HMMA, 4-stage) with fused bf16 hi/lo split epilogue
    {
        dim3 grid(QKV_COLS / 128, M_ROWS / 128);   // 18 x 32
        gemm_qkv_tc<<<grid, 256, GEMM_SMEM_BYTES>>>(b_kqv);
    }
    // tensor-core causal flash attention, writes g_sas directly
    {
        dim3 grid(SEQ / 128, BATCH * NHEAD);       // 16 x 24
        attn_tc<<<grid, 256, ATTN_SMEM_BYTES>>>();
    }
    // output projection (HMMA, 4-stage)
    {
        dim3 grid(DMODEL / 128, M_ROWS / 128);     // 6 x 32
        gemm_proj_tc<<<grid, 256, GEMM_SMEM_BYTES>>>(b_proj, out);
    }
}

// round 8
// speedup vs baseline: 3.4845x; 1.0120x over previous
#include <cuda_runtime.h>
#include <cuda_bf16.h>
#include <math.h>
#include <stdint.h>

#define BATCH 2
#define SEQ   2048
#define DMODEL 768
#define NHEAD 12
#define HDIM  64
#define M_ROWS (BATCH * SEQ)          // 4096
#define QKV_COLS (NHEAD * 3 * HDIM)   // 2304
#define K2 2304                       // expanded K' = 3*768
#define KCHUNK 32
#define NCHUNKS (K2 / KCHUNK)         // 72
#define SEGCH   (768 / KCHUNK)        // 24 chunks per split-K segment
#define APITCH 40                     // GEMM smem pitch (rows 32 wide + 8 pad)

// Q pre-scale: 1/sqrt(64) * log2(e)  (softmax computed in exp2 domain)
#define QSCALE 0.1803368801111244f

// ------------------------------ device scratch ------------------------------
__device__ __nv_bfloat16 g_xs [(size_t)M_ROWS   * K2]; // X  split  [hi|hi|lo]
__device__ __nv_bfloat16 g_wk [(size_t)QKV_COLS * K2]; // Wkqv split[hi|lo|hi]
__device__ __nv_bfloat16 g_wp [(size_t)DMODEL   * K2]; // Wproj split[hi|lo|hi]
__device__ __nv_bfloat16 g_sas[(size_t)M_ROWS   * K2]; // SA split  [hi|hi|lo]
__device__ float g_pp[3 * (size_t)M_ROWS * DMODEL];    // proj split-K partials

#define QKV_ELEMS ((size_t)BATCH * NHEAD * SEQ * HDIM)
__device__ __nv_bfloat16 g_qh[QKV_ELEMS], g_ql[QKV_ELEMS];
__device__ __nv_bfloat16 g_kh[QKV_ELEMS], g_kl[QKV_ELEMS];
__device__ __nv_bfloat16 g_vh[QKV_ELEMS], g_vl[QKV_ELEMS];

// ------------------------------ PTX helpers ---------------------------------
__device__ __forceinline__ uint32_t smem_u32(const void* p) {
    uint32_t a;
    asm("{ .reg .u64 t; cvta.to.shared.u64 t, %1; cvt.u32.u64 %0, t; }"
        : "=r"(a) : "l"(p));
    return a;
}
__device__ __forceinline__ void cp16(uint32_t dst, const void* src) {
    asm volatile("cp.async.cg.shared.global [%0], [%1], 16;"
                 :: "r"(dst), "l"(src) : "memory");
}
#define CP_COMMIT() asm volatile("cp.async.commit_group;" ::: "memory")
#define CP_WAIT2()  asm volatile("cp.async.wait_group 2;" ::: "memory")
#define CP_WAIT0()  asm volatile("cp.async.wait_group 0;" ::: "memory")

__device__ __forceinline__ void ldsm4(uint32_t addr, uint32_t r[4]) {
    asm volatile("ldmatrix.sync.aligned.m8n8.x4.shared.b16 {%0,%1,%2,%3}, [%4];"
                 : "=r"(r[0]), "=r"(r[1]), "=r"(r[2]), "=r"(r[3]) : "r"(addr));
}
__device__ __forceinline__ void ldsm4t(uint32_t addr, uint32_t r[4]) {
    asm volatile("ldmatrix.sync.aligned.m8n8.x4.trans.shared.b16 {%0,%1,%2,%3}, [%4];"
                 : "=r"(r[0]), "=r"(r[1]), "=r"(r[2]), "=r"(r[3]) : "r"(addr));
}
__device__ __forceinline__ void mma16816(float d[4], const uint32_t a[4],
                                         uint32_t b0, uint32_t b1) {
    asm volatile(
        "mma.sync.aligned.m16n8k16.row.col.f32.bf16.bf16.f32 "
        "{%0,%1,%2,%3}, {%4,%5,%6,%7}, {%8,%9}, {%0,%1,%2,%3};"
        : "+f"(d[0]), "+f"(d[1]), "+f"(d[2]), "+f"(d[3])
        : "r"(a[0]), "r"(a[1]), "r"(a[2]), "r"(a[3]), "r"(b0), "r"(b1));
}
__device__ __forceinline__ float ex2(float x) {
    float r;
    asm("ex2.approx.ftz.f32 %0, %1;" : "=f"(r) : "f"(x));
    return r;
}
__device__ __forceinline__ uint32_t prmt_hi2(uint32_t a, uint32_t b) {
    uint32_t r;
    asm("prmt.b32 %0, %1, %2, 0x7632;" : "=r"(r) : "r"(a), "r"(b));
    return r;
}

__device__ __forceinline__ void split_store(__nv_bfloat16* ph, __nv_bfloat16* pl,
                                            size_t idx, float f0, float f1) {
    __nv_bfloat16 h0 = __float2bfloat16(f0), h1 = __float2bfloat16(f1);
    float r0 = f0 - __bfloat162float(h0), r1 = f1 - __bfloat162float(h1);
    __nv_bfloat162 hv; hv.x = h0; hv.y = h1;
    __nv_bfloat162 lv; lv.x = __float2bfloat16(r0); lv.y = __float2bfloat16(r1);
    *(__nv_bfloat162*)&ph[idx] = hv;
    *(__nv_bfloat162*)&pl[idx] = lv;
}

// =============================================================================
// HMMA GEMM core: 128x128 tile, 256 threads, K-chunk 32, 4-stage cp.async ring,
// ONE __syncthreads per iteration. K range parameterized (split-K capable).
// =============================================================================
#define GEMM_SMEM_BYTES (8 * 5120 * 2)   // 81920

__device__ __forceinline__ void gemm_load_chunk(__nv_bfloat16* sm, int s,
                                                const __nv_bfloat16* __restrict__ A,
                                                const __nv_bfloat16* __restrict__ B,
                                                int m0, int n0, int k0, int t)
{
    __nv_bfloat16* As = sm + s * 5120;
    __nv_bfloat16* Bs = sm + 20480 + s * 5120;
#pragma unroll
    for (int i = 0; i < 2; i++) {
        const int idx = i * 256 + t;
        const int row = idx >> 2;
        const int c   = (idx & 3) * 8;
        cp16(smem_u32(&As[row * APITCH + c]), &A[(size_t)(m0 + row) * K2 + k0 + c]);
        cp16(smem_u32(&Bs[row * APITCH + c]), &B[(size_t)(n0 + row) * K2 + k0 + c]);
    }
}

__device__ __forceinline__ void gemm_mainloop(__nv_bfloat16* sm,
                                              const __nv_bfloat16* __restrict__ A,
                                              const __nv_bfloat16* __restrict__ B,
                                              int m0, int n0, int kbase, int nchunks,
                                              float acc[2][8][4])
{
    const int t    = threadIdx.x;
    const int lane = t & 31;
    const int wid  = t >> 5;
    const int wm   = wid >> 1;
    const int wn   = wid & 1;

#pragma unroll
    for (int i = 0; i < 2; i++)
#pragma unroll
        for (int j = 0; j < 8; j++)
#pragma unroll
            for (int e = 0; e < 4; e++) acc[i][j][e] = 0.f;

    const int g  = lane >> 3;
    const int l8 = lane & 7;
    const int a_row = l8 + ((g & 1) << 3);
    const int a_col = (g >> 1) << 3;
    const int b_row = l8 + ((g >> 1) << 3);
    const int b_col = (g & 1) << 3;

#pragma unroll
    for (int s = 0; s < 3; s++) {
        gemm_load_chunk(sm, s, A, B, m0, n0, kbase + s * KCHUNK, t);
        CP_COMMIT();
    }

    for (int ic = 0; ic < nchunks; ic++) {
        CP_WAIT2();
        __syncthreads();
        if (ic + 3 < nchunks)
            gemm_load_chunk(sm, (ic + 3) & 3, A, B, m0, n0,
                            kbase + (ic + 3) * KCHUNK, t);
        CP_COMMIT();

        const int buf = ic & 3;
        __nv_bfloat16* As = sm + buf * 5120;
        __nv_bfloat16* Bs = sm + 20480 + buf * 5120;
#pragma unroll
        for (int ks = 0; ks < 2; ks++) {
            const int k0 = ks * 16;
            uint32_t af[2][4];
#pragma unroll
            for (int mi = 0; mi < 2; mi++)
                ldsm4(smem_u32(&As[(wm * 32 + mi * 16 + a_row) * APITCH + k0 + a_col]),
                      af[mi]);
            uint32_t bfm[4][4];
#pragma unroll
            for (int np = 0; np < 4; np++)
                ldsm4(smem_u32(&Bs[(wn * 64 + np * 16 + b_row) * APITCH + k0 + b_col]),
                      bfm[np]);
#pragma unroll
            for (int mi = 0; mi < 2; mi++)
#pragma unroll
                for (int np = 0; np < 4; np++) {
                    mma16816(acc[mi][2 * np],     af[mi], bfm[np][0], bfm[np][1]);
                    mma16816(acc[mi][2 * np + 1], af[mi], bfm[np][2], bfm[np][3]);
                }
        }
    }
}

// -------------------- GEMM 1: QKV + split epilogue to planes -----------------
__global__ __launch_bounds__(256, 2)
void gemm_qkv_tc(const float* __restrict__ bias)
{
    extern __shared__ __nv_bfloat16 gsm[];
    const int m0 = blockIdx.y * 128, n0 = blockIdx.x * 128;

    float acc[2][8][4];
    gemm_mainloop(gsm, g_xs, g_wk, m0, n0, 0, NCHUNKS, acc);

    const int t = threadIdx.x, lane = t & 31, wid = t >> 5;
    const int wm = wid >> 1, wn = wid & 1;

#pragma unroll
    for (int mi = 0; mi < 2; mi++) {
        const int r0 = m0 + wm * 32 + mi * 16 + (lane >> 2);
#pragma unroll
        for (int nf = 0; nf < 8; nf++) {
            const int c   = n0 + wn * 64 + nf * 8 + (lane & 3) * 2;
            const int h   = c / 192;
            const int rr  = c % 192;
            const int sel = rr >> 6;       // 0=k, 1=q, 2=v
            const int o   = rr & 63;
            const float scale = (sel == 1) ? QSCALE : 1.0f;
            __nv_bfloat16 *ph = (sel == 0) ? g_kh : (sel == 1) ? g_qh : g_vh;
            __nv_bfloat16 *pl = (sel == 0) ? g_kl : (sel == 1) ? g_ql : g_vl;
            const float bx = bias[c], by = bias[c + 1];
#pragma unroll
            for (int rh = 0; rh < 2; rh++) {
                const int m  = r0 + rh * 8;
                const int bb = m >> 11, n = m & 2047;
                const size_t i0 = (((size_t)(bb * NHEAD + h) * SEQ) + n) * HDIM + o;
                split_store(ph, pl, i0,
                            (acc[mi][nf][2 * rh + 0] + bx) * scale,
                            (acc[mi][nf][2 * rh + 1] + by) * scale);
            }
        }
    }
}

// -------------------- GEMM 2: projection, split-K over 3 segments ------------
__global__ __launch_bounds__(256, 2)
void gemm_proj_seg()
{
    extern __shared__ __nv_bfloat16 gsm[];
    const int m0 = blockIdx.y * 128, n0 = blockIdx.x * 128;
    const int seg = blockIdx.z;

    float acc[2][8][4];
    gemm_mainloop(gsm, g_sas, g_wp, m0, n0, seg * 768, SEGCH, acc);

    const int t = threadIdx.x, lane = t & 31, wid = t >> 5;
    const int wm = wid >> 1, wn = wid & 1;
    float* pp = g_pp + (size_t)seg * M_ROWS * DMODEL;

#pragma unroll
    for (int mi = 0; mi < 2; mi++) {
        const int r0 = m0 + wm * 32 + mi * 16 + (lane >> 2);
#pragma unroll
        for (int nf = 0; nf < 8; nf++) {
            const int c = n0 + wn * 64 + nf * 8 + (lane & 3) * 2;
#pragma unroll
            for (int rh = 0; rh < 2; rh++) {
                const int m = r0 + rh * 8;
                float2 v;
                v.x = acc[mi][nf][2 * rh + 0];
                v.y = acc[mi][nf][2 * rh + 1];
                *(float2*)&pp[(size_t)m * DMODEL + c] = v;
            }
        }
    }
}

// fixed-order deterministic reduce + bias
__global__ __launch_bounds__(256)
void proj_reduce(const float* __restrict__ bias, float* __restrict__ out)
{
    const size_t i4 = ((size_t)blockIdx.x * 256 + threadIdx.x) * 4;
    const int c = (int)(i4 % DMODEL);
    float4 a = *(const float4*)&g_pp[i4];
    float4 b = *(const float4*)&g_pp[(size_t)M_ROWS * DMODEL + i4];
    float4 d = *(const float4*)&g_pp[2 * (size_t)M_ROWS * DMODEL + i4];
    float4 bv = *(const float4*)&bias[c];
    float4 r;
    r.x = (a.x + b.x) + (d.x + bv.x);
    r.y = (a.y + b.y) + (d.y + bv.y);
    r.z = (a.z + b.z) + (d.z + bv.z);
    r.w = (a.w + b.w) + (d.w + bv.w);
    *(float4*)&out[i4] = r;
}

// --------------------- fused conversion kernel (X, Wkqv, Wproj) --------------
__global__ __launch_bounds__(256)
void convert_all(const float* __restrict__ x,
                 const float* __restrict__ wk,
                 const float* __restrict__ wp)
{
    const int b = blockIdx.x;
    const float* src;
    __nv_bfloat16* out;
    int pattern;
    size_t gid;
    if (b < 3072)      { src = x;  out = g_xs; pattern = 0; gid = (size_t)b * 256; }
    else if (b < 4800) { src = wk; out = g_wk; pattern = 1; gid = (size_t)(b - 3072) * 256; }
    else               { src = wp; out = g_wp; pattern = 1; gid = (size_t)(b - 4800) * 256; }
    gid += threadIdx.x;

    const size_t r = gid / 192;
    const int    c = (int)(gid % 192) * 4;
    float4 xv4 = *(const float4*)&src[r * 768 + c];

    union BF4 { __nv_bfloat16 bb[4]; uint2 u; };
    BF4 hi, lo;
    float xv[4] = {xv4.x, xv4.y, xv4.z, xv4.w};
#pragma unroll
    for (int i = 0; i < 4; i++) {
        hi.bb[i] = __float2bfloat16(xv[i]);
        lo.bb[i] = __float2bfloat16(xv[i] - __bfloat162float(hi.bb[i]));
    }
    __nv_bfloat16* row = out + r * K2;
    *(uint2*)(row + c) = hi.u;
    if (pattern == 0) {
        *(uint2*)(row + 768  + c) = hi.u;
        *(uint2*)(row + 1536 + c) = lo.u;
    } else {
        *(uint2*)(row + 768  + c) = lo.u;
        *(uint2*)(row + 1536 + c) = hi.u;
    }
}

// =============================================================================
// Tensor-core causal flash attention (exp2 softmax), 2 CTA/SM target.
// 256 threads (8 warps x m16 rows), 64-key chunks, cp.async, 1 sync/chunk.
// Pitch 72 bf16 (144B). Qh@0, Ql@9216, stages @18432 (plane 4608, stage 18432).
// Total 110592 B -> 2 CTAs = 221184 B <= 228KB SM budget.
// =============================================================================
#define VPITCH 72
#define AQH 0
#define AQL 9216
#define ACH 18432
#define PLSTRIDE 4608
#define STSTRIDE 18432
#define ATTN_SMEM_BYTES (55296 * 2)

__global__ __launch_bounds__(256, 2)
void attn_tc()
{
    extern __shared__ __nv_bfloat16 sm[];
    const int bh = blockIdx.y;
    const int q0 = blockIdx.x * 128;
    const int t = threadIdx.x, lane = t & 31, wid = t >> 5;
    const int nch = (q0 >> 6) + 2;

    const size_t bhoff = (size_t)bh * SEQ * HDIM;
    const __nv_bfloat16 *Qh = g_qh + bhoff, *Ql = g_ql + bhoff;
    const __nv_bfloat16 *Kh = g_kh + bhoff, *Kl = g_kl + bhoff;
    const __nv_bfloat16 *Vh = g_vh + bhoff, *Vl = g_vl + bhoff;

    // ---- prologue: Q (both planes) + chunk 0 ----
#pragma unroll
    for (int i = 0; i < 8; i++) {
        const int idx = t + i * 256;
        const int plane = idx >> 10;
        const int w = idx & 1023;
        const int r = w >> 3, c = (w & 7) * 8;
        const __nv_bfloat16* src = (plane ? Ql : Qh) + (size_t)(q0 + r) * HDIM + c;
        cp16(smem_u32(&sm[(plane ? AQL : AQH) + r * VPITCH + c]), src);
    }
#pragma unroll
    for (int i = 0; i < 8; i++) {
        const int idx = t + i * 256;
        const int plane = idx >> 9;
        const int w = idx & 511;
        const int r = w >> 3, c = (w & 7) * 8;
        const __nv_bfloat16* src =
            ((plane == 0) ? Kh : (plane == 1) ? Kl : (plane == 2) ? Vh : Vl)
            + (size_t)r * HDIM + c;
        cp16(smem_u32(&sm[ACH + plane * PLSTRIDE + r * VPITCH + c]), src);
    }
    CP_COMMIT();
    CP_WAIT0();
    __syncthreads();

    float O[8][4];
#pragma unroll
    for (int nt = 0; nt < 8; nt++)
#pragma unroll
        for (int e = 0; e < 4; e++) O[nt][e] = 0.f;
    float mrun[2] = {-1e30f, -1e30f};
    float lrun[2] = {0.f, 0.f};

    const int g  = lane >> 3;
    const int l8 = lane & 7;
    const int a_row = l8 + ((g & 1) << 3);
    const int a_col = (g >> 1) << 3;
    const int b_row = l8 + ((g >> 1) << 3);
    const int b_col = (g & 1) << 3;
    const int v_row = l8 + ((g & 1) << 3);
    const int v_col = (g >> 1) << 3;

    for (int ic = 0; ic < nch; ic++) {
        const int buf = ic & 1;
        if (ic > 0) {
            CP_WAIT0();
            __syncthreads();
        }
        if (ic + 1 < nch) {
            const int s1 = (ic + 1) * 64;
            const int nb = ACH + (buf ^ 1) * STSTRIDE;
#pragma unroll
            for (int i = 0; i < 8; i++) {
                const int idx = t + i * 256;
                const int plane = idx >> 9;
                const int w = idx & 511;
                const int r = w >> 3, c = (w & 7) * 8;
                const __nv_bfloat16* src =
                    ((plane == 0) ? Kh : (plane == 1) ? Kl : (plane == 2) ? Vh : Vl)
                    + (size_t)(s1 + r) * HDIM + c;
                cp16(smem_u32(&sm[nb + plane * PLSTRIDE + r * VPITCH + c]), src);
            }
        }
        CP_COMMIT();

        const int s0 = ic * 64;
        // warp-level causal skip: this warp's rows end before the chunk starts
        if (s0 > q0 + wid * 16 + 15) continue;   // no barriers below in this iter

        const int kbase = ACH + buf * STSTRIDE;
        const int vbase = kbase + 2 * PLSTRIDE;

        // ---- S = Qh*Kh + Qh*Kl + Ql*Kh ----
        float S[8][4];
#pragma unroll
        for (int nt = 0; nt < 8; nt++)
#pragma unroll
            for (int e = 0; e < 4; e++) S[nt][e] = 0.f;

#pragma unroll
        for (int kt = 0; kt < 4; kt++) {
            uint32_t ah[4], al[4];
            ldsm4(smem_u32(&sm[AQH + (wid * 16 + a_row) * VPITCH + kt * 16 + a_col]), ah);
            ldsm4(smem_u32(&sm[AQL + (wid * 16 + a_row) * VPITCH + kt * 16 + a_col]), al);
#pragma unroll
            for (int np = 0; np < 4; np++) {
                uint32_t kh4[4], kl4[4];
                ldsm4(smem_u32(&sm[kbase + (np * 16 + b_row) * VPITCH + kt * 16 + b_col]), kh4);
                ldsm4(smem_u32(&sm[kbase + PLSTRIDE + (np * 16 + b_row) * VPITCH + kt * 16 + b_col]), kl4);
                mma16816(S[2 * np],     ah, kh4[0], kh4[1]);
                mma16816(S[2 * np + 1], ah, kh4[2], kh4[3]);
                mma16816(S[2 * np],     ah, kl4[0], kl4[1]);
                mma16816(S[2 * np + 1], ah, kl4[2], kl4[3]);
                mma16816(S[2 * np],     al, kh4[0], kh4[1]);
                mma16816(S[2 * np + 1], al, kh4[2], kh4[3]);
            }
        }

        // ---- causal mask ----
        const int rowbase = q0 + wid * 16 + (lane >> 2);
        if (s0 + 63 > q0 + wid * 16) {
#pragma unroll
            for (int nt = 0; nt < 8; nt++)
#pragma unroll
                for (int e = 0; e < 4; e++) {
                    const int row = rowbase + ((e >> 1) << 3);
                    const int col = s0 + nt * 8 + ((lane & 3) << 1) + (e & 1);
                    if (col > row) S[nt][e] = -1e30f;
                }
        }

        // ---- online softmax (base-2) ----
        float rmax[2] = {-1e30f, -1e30f};
#pragma unroll
        for (int nt = 0; nt < 8; nt++) {
            rmax[0] = fmaxf(rmax[0], fmaxf(S[nt][0], S[nt][1]));
            rmax[1] = fmaxf(rmax[1], fmaxf(S[nt][2], S[nt][3]));
        }
        float alpha[2];
#pragma unroll
        for (int r = 0; r < 2; r++) {
            rmax[r] = fmaxf(rmax[r], __shfl_xor_sync(0xffffffffu, rmax[r], 1));
            rmax[r] = fmaxf(rmax[r], __shfl_xor_sync(0xffffffffu, rmax[r], 2));
            const float mn = fmaxf(mrun[r], rmax[r]);
            alpha[r] = ex2(mrun[r] - mn);
            mrun[r] = mn;
        }
        float lsum[2] = {0.f, 0.f};
#pragma unroll
        for (int nt = 0; nt < 8; nt++)
#pragma unroll
            for (int e = 0; e < 4; e++) {
                const float p = ex2(S[nt][e] - mrun[e >> 1]);
                S[nt][e] = p;
                lsum[e >> 1] += p;
            }
#pragma unroll
        for (int r = 0; r < 2; r++) {
            lsum[r] += __shfl_xor_sync(0xffffffffu, lsum[r], 1);
            lsum[r] += __shfl_xor_sync(0xffffffffu, lsum[r], 2);
            lrun[r] = lrun[r] * alpha[r] + lsum[r];
        }
#pragma unroll
        for (int nt = 0; nt < 8; nt++)
#pragma unroll
            for (int e = 0; e < 4; e++) O[nt][e] *= alpha[e >> 1];

        // ---- PV: O += Ph*Vh + Ph*Vl + Pl*Vh ----
#pragma unroll
        for (int kt = 0; kt < 4; kt++) {
            uint32_t ph[4], pl[4];
            {
                const float* sp0 = S[2 * kt];
                const float* sp1 = S[2 * kt + 1];
#pragma unroll
                for (int h2 = 0; h2 < 2; h2++) {
                    const float* sp = h2 ? sp1 : sp0;
#pragma unroll
                    for (int pp = 0; pp < 2; pp++) {
                        const float f0 = sp[2 * pp], f1 = sp[2 * pp + 1];
                        const uint32_t u0 = __float_as_uint(f0);
                        const uint32_t u1 = __float_as_uint(f1);
                        ph[2 * h2 + pp] = prmt_hi2(u0, u1);
                        const float l0 = f0 - __uint_as_float(u0 & 0xFFFF0000u);
                        const float l1 = f1 - __uint_as_float(u1 & 0xFFFF0000u);
                        pl[2 * h2 + pp] = prmt_hi2(__float_as_uint(l0),
                                                   __float_as_uint(l1));
                    }
                }
            }
#pragma unroll
            for (int hp = 0; hp < 4; hp++) {
                uint32_t vh4[4], vl4[4];
                ldsm4t(smem_u32(&sm[vbase + (kt * 16 + v_row) * VPITCH + hp * 16 + v_col]), vh4);
                ldsm4t(smem_u32(&sm[vbase + PLSTRIDE + (kt * 16 + v_row) * VPITCH + hp * 16 + v_col]), vl4);
                mma16816(O[2 * hp],     ph, vh4[0], vh4[1]);
                mma16816(O[2 * hp + 1], ph, vh4[2], vh4[3]);
                mma16816(O[2 * hp],     ph, vl4[0], vl4[1]);
                mma16816(O[2 * hp + 1], ph, vl4[2], vl4[3]);
                mma16816(O[2 * hp],     pl, vh4[0], vh4[1]);
                mma16816(O[2 * hp + 1], pl, vh4[2], vh4[3]);
            }
        }
    }

    // ---- epilogue: normalize, split, write g_sas [hi | hi | lo] ----
    const int b = bh / NHEAD;
    const int h = bh % NHEAD;
#pragma unroll
    for (int r = 0; r < 2; r++) {
        const float inv = 1.f / lrun[r];
        const int n = q0 + wid * 16 + (lane >> 2) + r * 8;
        __nv_bfloat16* rowp = g_sas + (size_t)(b * SEQ + n) * K2;
#pragma unroll
        for (int nt = 0; nt < 8; nt++) {
            const int c = h * HDIM + nt * 8 + ((lane & 3) << 1);
            const float f0 = O[nt][2 * r + 0] * inv;
            const float f1 = O[nt][2 * r + 1] * inv;
            __nv_bfloat16 h0 = __float2bfloat16(f0), h1 = __float2bfloat16(f1);
            __nv_bfloat162 hv; hv.x = h0; hv.y = h1;
            __nv_bfloat162 lv;
            lv.x = __float2bfloat16(f0 - __bfloat162float(h0));
            lv.y = __float2bfloat16(f1 - __bfloat162float(h1));
            *(__nv_bfloat162*)&rowp[c]        = hv;
            *(__nv_bfloat162*)&rowp[768 + c]  = hv;
            *(__nv_bfloat162*)&rowp[1536 + c] = lv;
        }
    }
}

// ---------------------------------------------------------------------------
extern "C" void kernel_launch(void* const* d_in, const int* in_sizes, int n_in,
                              void* d_out, int out_size)
{
    const float* x      = (const float*)d_in[0];  // [B, N, D]
    const float* W_kqv  = (const float*)d_in[1];  // [H, 3*HD, D]
    const float* b_kqv  = (const float*)d_in[2];  // [H, 3*HD]
    const float* W_proj = (const float*)d_in[3];  // [D, D]
    const float* b_proj = (const float*)d_in[4];  // [D]
    float* out = (float*)d_out;

    (void)in_sizes; (void)n_in; (void)out_size;

    cudaFuncSetAttribute(attn_tc, cudaFuncAttributeMaxDynamicSharedMemorySize,
                         ATTN_SMEM_BYTES);
    cudaFuncSetAttribute(gemm_qkv_tc, cudaFuncAttributeMaxDynamicSharedMemorySize,
                         GEMM_SMEM_BYTES);
    cudaFuncSetAttribute(gemm_proj_seg, cudaFuncAttributeMaxDynamicSharedMemorySize,
                         GEMM_SMEM_BYTES);

    // fused split conversions (X, Wkqv, Wproj)
    convert_all<<<5376, 256>>>(x, W_kqv, W_proj);

    // QKV projection (HMMA, 4-stage) with fused bf16 hi/lo split epilogue
    {
        dim3 grid(QKV_COLS / 128, M_ROWS / 128);   // 18 x 32
        gemm_qkv_tc<<<grid, 256, GEMM_SMEM_BYTES>>>(b_kqv);
    }
    // tensor-core causal flash attention (2 CTA/SM), writes g_sas directly
    {
        dim3 grid(SEQ / 128, BATCH * NHEAD);       // 16 x 24
        attn_tc<<<grid, 256, ATTN_SMEM_BYTES>>>();
    }
    // output projection: split-K x3 + deterministic reduce
    {
        dim3 grid(DMODEL / 128, M_ROWS / 128, 3);  // 6 x 32 x 3
        gemm_proj_seg<<<grid, 256, GEMM_SMEM_BYTES>>>();
        proj_reduce<<<3072, 256>>>(b_proj, out);
    }
}

// round 9
// speedup vs baseline: 3.8205x; 1.0964x over previous
#include <cuda_runtime.h>
#include <cuda_bf16.h>
#include <math.h>
#include <stdint.h>

#define BATCH 2
#define SEQ   2048
#define DMODEL 768
#define NHEAD 12
#define HDIM  64
#define M_ROWS (BATCH * SEQ)          // 4096
#define QKV_COLS (NHEAD * 3 * HDIM)   // 2304
#define K2 2304                       // expanded K' = 3*768
#define KCHUNK 64
#define NCHUNKS (K2 / KCHUNK)         // 36
#define SEGCH   (768 / KCHUNK)        // 12 chunks per split-K segment
#define GPITCH 72                     // smem pitch (144B): conflict-free ldmatrix

// Q pre-scale: 1/sqrt(64) * log2(e)  (softmax computed in exp2 domain)
#define QSCALE 0.1803368801111244f

// ------------------------------ device scratch ------------------------------
__device__ __nv_bfloat16 g_xs [(size_t)M_ROWS   * K2]; // X  split  [hi|hi|lo]
__device__ __nv_bfloat16 g_wk [(size_t)QKV_COLS * K2]; // Wkqv split[hi|lo|hi]
__device__ __nv_bfloat16 g_wp [(size_t)DMODEL   * K2]; // Wproj split[hi|lo|hi]
__device__ __nv_bfloat16 g_sas[(size_t)M_ROWS   * K2]; // SA split  [hi|hi|lo]
__device__ float g_pp[3 * (size_t)M_ROWS * DMODEL];    // proj split-K partials

#define QKV_ELEMS ((size_t)BATCH * NHEAD * SEQ * HDIM)
__device__ __nv_bfloat16 g_qh[QKV_ELEMS], g_ql[QKV_ELEMS];
__device__ __nv_bfloat16 g_kh[QKV_ELEMS], g_kl[QKV_ELEMS];
__device__ __nv_bfloat16 g_vh[QKV_ELEMS], g_vl[QKV_ELEMS];

// ------------------------------ PTX helpers ---------------------------------
__device__ __forceinline__ uint32_t smem_u32(const void* p) {
    uint32_t a;
    asm("{ .reg .u64 t; cvta.to.shared.u64 t, %1; cvt.u32.u64 %0, t; }"
        : "=r"(a) : "l"(p));
    return a;
}
__device__ __forceinline__ void cp16(uint32_t dst, const void* src) {
    asm volatile("cp.async.cg.shared.global [%0], [%1], 16;"
                 :: "r"(dst), "l"(src) : "memory");
}
#define CP_COMMIT() asm volatile("cp.async.commit_group;" ::: "memory")
#define CP_WAIT1()  asm volatile("cp.async.wait_group 1;" ::: "memory")
#define CP_WAIT0()  asm volatile("cp.async.wait_group 0;" ::: "memory")

__device__ __forceinline__ void ldsm4(uint32_t addr, uint32_t r[4]) {
    asm volatile("ldmatrix.sync.aligned.m8n8.x4.shared.b16 {%0,%1,%2,%3}, [%4];"
                 : "=r"(r[0]), "=r"(r[1]), "=r"(r[2]), "=r"(r[3]) : "r"(addr));
}
__device__ __forceinline__ void ldsm4t(uint32_t addr, uint32_t r[4]) {
    asm volatile("ldmatrix.sync.aligned.m8n8.x4.trans.shared.b16 {%0,%1,%2,%3}, [%4];"
                 : "=r"(r[0]), "=r"(r[1]), "=r"(r[2]), "=r"(r[3]) : "r"(addr));
}
__device__ __forceinline__ void mma16816(float d[4], const uint32_t a[4],
                                         uint32_t b0, uint32_t b1) {
    asm volatile(
        "mma.sync.aligned.m16n8k16.row.col.f32.bf16.bf16.f32 "
        "{%0,%1,%2,%3}, {%4,%5,%6,%7}, {%8,%9}, {%0,%1,%2,%3};"
        : "+f"(d[0]), "+f"(d[1]), "+f"(d[2]), "+f"(d[3])
        : "r"(a[0]), "r"(a[1]), "r"(a[2]), "r"(a[3]), "r"(b0), "r"(b1));
}
__device__ __forceinline__ float ex2(float x) {
    float r;
    asm("ex2.approx.ftz.f32 %0, %1;" : "=f"(r) : "f"(x));
    return r;
}
__device__ __forceinline__ uint32_t prmt_hi2(uint32_t a, uint32_t b) {
    uint32_t r;
    asm("prmt.b32 %0, %1, %2, 0x7632;" : "=r"(r) : "r"(a), "r"(b));
    return r;
}

__device__ __forceinline__ void split_store(__nv_bfloat16* ph, __nv_bfloat16* pl,
                                            size_t idx, float f0, float f1) {
    __nv_bfloat16 h0 = __float2bfloat16(f0), h1 = __float2bfloat16(f1);
    float r0 = f0 - __bfloat162float(h0), r1 = f1 - __bfloat162float(h1);
    __nv_bfloat162 hv; hv.x = h0; hv.y = h1;
    __nv_bfloat162 lv; lv.x = __float2bfloat16(r0); lv.y = __float2bfloat16(r1);
    *(__nv_bfloat162*)&ph[idx] = hv;
    *(__nv_bfloat162*)&pl[idx] = lv;
}

// =============================================================================
// HMMA GEMM core: 128x128 tile, 256 threads, K-chunk 64, 3-stage cp.async ring,
// one __syncthreads + one wait_group per 64-K chunk.
// smem (bf16 elems): A stage s @ s*9216, B stage s @ 27648 + s*9216.
// Total 6*9216*2 = 110592 B -> 2 CTA/SM.
// =============================================================================
#define GEMM_SMEM_BYTES (6 * 9216 * 2)   // 110592

__device__ __forceinline__ void gemm_load_chunk(__nv_bfloat16* sm, int s,
                                                const __nv_bfloat16* __restrict__ A,
                                                const __nv_bfloat16* __restrict__ B,
                                                int m0, int n0, int k0, int t)
{
    __nv_bfloat16* As = sm + s * 9216;
    __nv_bfloat16* Bs = sm + 27648 + s * 9216;
#pragma unroll
    for (int i = 0; i < 4; i++) {
        const int idx = i * 256 + t;
        const int row = idx >> 3;
        const int c   = (idx & 7) * 8;
        cp16(smem_u32(&As[row * GPITCH + c]), &A[(size_t)(m0 + row) * K2 + k0 + c]);
        cp16(smem_u32(&Bs[row * GPITCH + c]), &B[(size_t)(n0 + row) * K2 + k0 + c]);
    }
}

__device__ __forceinline__ void gemm_mainloop(__nv_bfloat16* sm,
                                              const __nv_bfloat16* __restrict__ A,
                                              const __nv_bfloat16* __restrict__ B,
                                              int m0, int n0, int kbase, int nchunks,
                                              float acc[2][8][4])
{
    const int t    = threadIdx.x;
    const int lane = t & 31;
    const int wid  = t >> 5;
    const int wm   = wid >> 1;
    const int wn   = wid & 1;

#pragma unroll
    for (int i = 0; i < 2; i++)
#pragma unroll
        for (int j = 0; j < 8; j++)
#pragma unroll
            for (int e = 0; e < 4; e++) acc[i][j][e] = 0.f;

    const int g  = lane >> 3;
    const int l8 = lane & 7;
    const int a_row = l8 + ((g & 1) << 3);
    const int a_col = (g >> 1) << 3;
    const int b_row = l8 + ((g >> 1) << 3);
    const int b_col = (g & 1) << 3;

    gemm_load_chunk(sm, 0, A, B, m0, n0, kbase, t);
    CP_COMMIT();
    gemm_load_chunk(sm, 1, A, B, m0, n0, kbase + KCHUNK, t);
    CP_COMMIT();

    for (int ic = 0; ic < nchunks; ic++) {
        CP_WAIT1();                 // chunk ic resident
        __syncthreads();            // readers of the stage we're about to write done
        if (ic + 2 < nchunks)
            gemm_load_chunk(sm, (ic + 2) % 3, A, B, m0, n0,
                            kbase + (ic + 2) * KCHUNK, t);
        CP_COMMIT();

        const int buf = ic % 3;
        __nv_bfloat16* As = sm + buf * 9216;
        __nv_bfloat16* Bs = sm + 27648 + buf * 9216;
#pragma unroll
        for (int ks = 0; ks < 4; ks++) {
            const int k0 = ks * 16;
            uint32_t af[2][4];
#pragma unroll
            for (int mi = 0; mi < 2; mi++)
                ldsm4(smem_u32(&As[(wm * 32 + mi * 16 + a_row) * GPITCH + k0 + a_col]),
                      af[mi]);
            uint32_t bfm[4][4];
#pragma unroll
            for (int np = 0; np < 4; np++)
                ldsm4(smem_u32(&Bs[(wn * 64 + np * 16 + b_row) * GPITCH + k0 + b_col]),
                      bfm[np]);
#pragma unroll
            for (int mi = 0; mi < 2; mi++)
#pragma unroll
                for (int np = 0; np < 4; np++) {
                    mma16816(acc[mi][2 * np],     af[mi], bfm[np][0], bfm[np][1]);
                    mma16816(acc[mi][2 * np + 1], af[mi], bfm[np][2], bfm[np][3]);
                }
        }
    }
}

// -------------------- GEMM 1: QKV + split epilogue to planes -----------------
__global__ __launch_bounds__(256, 2)
void gemm_qkv_tc(const float* __restrict__ bias)
{
    extern __shared__ __nv_bfloat16 gsm[];
    const int m0 = blockIdx.y * 128, n0 = blockIdx.x * 128;

    float acc[2][8][4];
    gemm_mainloop(gsm, g_xs, g_wk, m0, n0, 0, NCHUNKS, acc);

    const int t = threadIdx.x, lane = t & 31, wid = t >> 5;
    const int wm = wid >> 1, wn = wid & 1;

#pragma unroll
    for (int mi = 0; mi < 2; mi++) {
        const int r0 = m0 + wm * 32 + mi * 16 + (lane >> 2);
#pragma unroll
        for (int nf = 0; nf < 8; nf++) {
            const int c   = n0 + wn * 64 + nf * 8 + (lane & 3) * 2;
            const int h   = c / 192;
            const int rr  = c % 192;
            const int sel = rr >> 6;       // 0=k, 1=q, 2=v
            const int o   = rr & 63;
            const float scale = (sel == 1) ? QSCALE : 1.0f;
            __nv_bfloat16 *ph = (sel == 0) ? g_kh : (sel == 1) ? g_qh : g_vh;
            __nv_bfloat16 *pl = (sel == 0) ? g_kl : (sel == 1) ? g_ql : g_vl;
            const float bx = bias[c], by = bias[c + 1];
#pragma unroll
            for (int rh = 0; rh < 2; rh++) {
                const int m  = r0 + rh * 8;
                const int bb = m >> 11, n = m & 2047;
                const size_t i0 = (((size_t)(bb * NHEAD + h) * SEQ) + n) * HDIM + o;
                split_store(ph, pl, i0,
                            (acc[mi][nf][2 * rh + 0] + bx) * scale,
                            (acc[mi][nf][2 * rh + 1] + by) * scale);
            }
        }
    }
}

// -------------------- GEMM 2: projection, split-K over 3 segments ------------
__global__ __launch_bounds__(256, 2)
void gemm_proj_seg()
{
    extern __shared__ __nv_bfloat16 gsm[];
    const int m0 = blockIdx.y * 128, n0 = blockIdx.x * 128;
    const int seg = blockIdx.z;

    float acc[2][8][4];
    gemm_mainloop(gsm, g_sas, g_wp, m0, n0, seg * 768, SEGCH, acc);

    const int t = threadIdx.x, lane = t & 31, wid = t >> 5;
    const int wm = wid >> 1, wn = wid & 1;
    float* pp = g_pp + (size_t)seg * M_ROWS * DMODEL;

#pragma unroll
    for (int mi = 0; mi < 2; mi++) {
        const int r0 = m0 + wm * 32 + mi * 16 + (lane >> 2);
#pragma unroll
        for (int nf = 0; nf < 8; nf++) {
            const int c = n0 + wn * 64 + nf * 8 + (lane & 3) * 2;
#pragma unroll
            for (int rh = 0; rh < 2; rh++) {
                const int m = r0 + rh * 8;
                float2 v;
                v.x = acc[mi][nf][2 * rh + 0];
                v.y = acc[mi][nf][2 * rh + 1];
                *(float2*)&pp[(size_t)m * DMODEL + c] = v;
            }
        }
    }
}

// fixed-order deterministic reduce + bias
__global__ __launch_bounds__(256)
void proj_reduce(const float* __restrict__ bias, float* __restrict__ out)
{
    const size_t i4 = ((size_t)blockIdx.x * 256 + threadIdx.x) * 4;
    const int c = (int)(i4 % DMODEL);
    float4 a = *(const float4*)&g_pp[i4];
    float4 b = *(const float4*)&g_pp[(size_t)M_ROWS * DMODEL + i4];
    float4 d = *(const float4*)&g_pp[2 * (size_t)M_ROWS * DMODEL + i4];
    float4 bv = *(const float4*)&bias[c];
    float4 r;
    r.x = (a.x + b.x) + (d.x + bv.x);
    r.y = (a.y + b.y) + (d.y + bv.y);
    r.z = (a.z + b.z) + (d.z + bv.z);
    r.w = (a.w + b.w) + (d.w + bv.w);
    *(float4*)&out[i4] = r;
}

// --------------------- fused conversion kernel (X, Wkqv, Wproj) --------------
__global__ __launch_bounds__(256)
void convert_all(const float* __restrict__ x,
                 const float* __restrict__ wk,
                 const float* __restrict__ wp)
{
    const int b = blockIdx.x;
    const float* src;
    __nv_bfloat16* out;
    int pattern;
    size_t gid;
    if (b < 3072)      { src = x;  out = g_xs; pattern = 0; gid = (size_t)b * 256; }
    else if (b < 4800) { src = wk; out = g_wk; pattern = 1; gid = (size_t)(b - 3072) * 256; }
    else               { src = wp; out = g_wp; pattern = 1; gid = (size_t)(b - 4800) * 256; }
    gid += threadIdx.x;

    const size_t r = gid / 192;
    const int    c = (int)(gid % 192) * 4;
    float4 xv4 = *(const float4*)&src[r * 768 + c];

    union BF4 { __nv_bfloat16 bb[4]; uint2 u; };
    BF4 hi, lo;
    float xv[4] = {xv4.x, xv4.y, xv4.z, xv4.w};
#pragma unroll
    for (int i = 0; i < 4; i++) {
        hi.bb[i] = __float2bfloat16(xv[i]);
        lo.bb[i] = __float2bfloat16(xv[i] - __bfloat162float(hi.bb[i]));
    }
    __nv_bfloat16* row = out + r * K2;
    *(uint2*)(row + c) = hi.u;
    if (pattern == 0) {
        *(uint2*)(row + 768  + c) = hi.u;
        *(uint2*)(row + 1536 + c) = lo.u;
    } else {
        *(uint2*)(row + 768  + c) = lo.u;
        *(uint2*)(row + 1536 + c) = hi.u;
    }
}

// =============================================================================
// Tensor-core causal flash attention (exp2 softmax).
// 128 threads (4 warps x m16 rows = 64-row q-tile), 64-key chunks, cp.async
// double-buffer, 1 sync/chunk, Q fragments hoisted (register-resident).
// smem (bf16 elems): Qh@0 (64x72), Ql@4608, stages @9216 (plane 4608,
// stage 18432). Total 46080 elems = 92160 B -> 2 CTA/SM, 256-reg budget.
// =============================================================================
#define VPITCH 72
#define AQH 0
#define AQL 4608
#define ACH 9216
#define PLSTRIDE 4608
#define STSTRIDE 18432
#define ATTN_SMEM_BYTES (46080 * 2)   // 92160

__global__ __launch_bounds__(128, 2)
void attn_tc()
{
    extern __shared__ __nv_bfloat16 sm[];
    const int bh = blockIdx.y;
    const int q0 = blockIdx.x * 64;
    const int t = threadIdx.x, lane = t & 31, wid = t >> 5;
    const int nch = (q0 >> 6) + 1;

    const size_t bhoff = (size_t)bh * SEQ * HDIM;
    const __nv_bfloat16 *Qh = g_qh + bhoff, *Ql = g_ql + bhoff;
    const __nv_bfloat16 *Kh = g_kh + bhoff, *Kl = g_kl + bhoff;
    const __nv_bfloat16 *Vh = g_vh + bhoff, *Vl = g_vl + bhoff;

    // ---- prologue: Q (both planes, 64 rows) + chunk 0 ----
#pragma unroll
    for (int i = 0; i < 8; i++) {
        const int idx = t + i * 128;          // 1024: plane = idx>>9
        const int plane = idx >> 9;
        const int w = idx & 511;
        const int r = w >> 3, c = (w & 7) * 8;
        const __nv_bfloat16* src = (plane ? Ql : Qh) + (size_t)(q0 + r) * HDIM + c;
        cp16(smem_u32(&sm[(plane ? AQL : AQH) + r * VPITCH + c]), src);
    }
#pragma unroll
    for (int i = 0; i < 16; i++) {
        const int idx = t + i * 128;          // 2048: plane = idx>>9
        const int plane = idx >> 9;
        const int w = idx & 511;
        const int r = w >> 3, c = (w & 7) * 8;
        const __nv_bfloat16* src =
            ((plane == 0) ? Kh : (plane == 1) ? Kl : (plane == 2) ? Vh : Vl)
            + (size_t)r * HDIM + c;
        cp16(smem_u32(&sm[ACH + plane * PLSTRIDE + r * VPITCH + c]), src);
    }
    CP_COMMIT();
    CP_WAIT0();
    __syncthreads();

    const int g  = lane >> 3;
    const int l8 = lane & 7;
    const int a_row = l8 + ((g & 1) << 3);
    const int a_col = (g >> 1) << 3;
    const int b_row = l8 + ((g >> 1) << 3);
    const int b_col = (g & 1) << 3;
    const int v_row = l8 + ((g & 1) << 3);
    const int v_col = (g >> 1) << 3;

    // ---- hoist Q fragments (loop-invariant) ----
    uint32_t qhf[4][4], qlf[4][4];
#pragma unroll
    for (int kt = 0; kt < 4; kt++) {
        ldsm4(smem_u32(&sm[AQH + (wid * 16 + a_row) * VPITCH + kt * 16 + a_col]), qhf[kt]);
        ldsm4(smem_u32(&sm[AQL + (wid * 16 + a_row) * VPITCH + kt * 16 + a_col]), qlf[kt]);
    }

    float O[8][4];
#pragma unroll
    for (int nt = 0; nt < 8; nt++)
#pragma unroll
        for (int e = 0; e < 4; e++) O[nt][e] = 0.f;
    float mrun[2] = {-1e30f, -1e30f};
    float lrun[2] = {0.f, 0.f};

    for (int ic = 0; ic < nch; ic++) {
        const int buf = ic & 1;
        if (ic > 0) {
            CP_WAIT0();
            __syncthreads();
        }
        if (ic + 1 < nch) {
            const int s1 = (ic + 1) * 64;
            const int nb = ACH + (buf ^ 1) * STSTRIDE;
#pragma unroll
            for (int i = 0; i < 16; i++) {
                const int idx = t + i * 128;
                const int plane = idx >> 9;
                const int w = idx & 511;
                const int r = w >> 3, c = (w & 7) * 8;
                const __nv_bfloat16* src =
                    ((plane == 0) ? Kh : (plane == 1) ? Kl : (plane == 2) ? Vh : Vl)
                    + (size_t)(s1 + r) * HDIM + c;
                cp16(smem_u32(&sm[nb + plane * PLSTRIDE + r * VPITCH + c]), src);
            }
        }
        CP_COMMIT();

        const int s0 = ic * 64;
        const int kbase = ACH + buf * STSTRIDE;
        const int vbase = kbase + 2 * PLSTRIDE;

        // ---- S = Qh*Kh + Qh*Kl + Ql*Kh ----
        float S[8][4];
#pragma unroll
        for (int nt = 0; nt < 8; nt++)
#pragma unroll
            for (int e = 0; e < 4; e++) S[nt][e] = 0.f;

#pragma unroll
        for (int kt = 0; kt < 4; kt++) {
#pragma unroll
            for (int np = 0; np < 4; np++) {
                uint32_t kh4[4], kl4[4];
                ldsm4(smem_u32(&sm[kbase + (np * 16 + b_row) * VPITCH + kt * 16 + b_col]), kh4);
                ldsm4(smem_u32(&sm[kbase + PLSTRIDE + (np * 16 + b_row) * VPITCH + kt * 16 + b_col]), kl4);
                mma16816(S[2 * np],     qhf[kt], kh4[0], kh4[1]);
                mma16816(S[2 * np + 1], qhf[kt], kh4[2], kh4[3]);
                mma16816(S[2 * np],     qhf[kt], kl4[0], kl4[1]);
                mma16816(S[2 * np + 1], qhf[kt], kl4[2], kl4[3]);
                mma16816(S[2 * np],     qlf[kt], kh4[0], kh4[1]);
                mma16816(S[2 * np + 1], qlf[kt], kh4[2], kh4[3]);
            }
        }

        // ---- causal mask (only the diagonal chunk needs it) ----
        const int rowbase = q0 + wid * 16 + (lane >> 2);
        if (s0 + 63 > q0 + wid * 16) {
#pragma unroll
            for (int nt = 0; nt < 8; nt++)
#pragma unroll
                for (int e = 0; e < 4; e++) {
                    const int row = rowbase + ((e >> 1) << 3);
                    const int col = s0 + nt * 8 + ((lane & 3) << 1) + (e & 1);
                    if (col > row) S[nt][e] = -1e30f;
                }
        }

        // ---- online softmax (base-2) ----
        float rmax[2] = {-1e30f, -1e30f};
#pragma unroll
        for (int nt = 0; nt < 8; nt++) {
            rmax[0] = fmaxf(rmax[0], fmaxf(S[nt][0], S[nt][1]));
            rmax[1] = fmaxf(rmax[1], fmaxf(S[nt][2], S[nt][3]));
        }
        float alpha[2];
#pragma unroll
        for (int r = 0; r < 2; r++) {
            rmax[r] = fmaxf(rmax[r], __shfl_xor_sync(0xffffffffu, rmax[r], 1));
            rmax[r] = fmaxf(rmax[r], __shfl_xor_sync(0xffffffffu, rmax[r], 2));
            const float mn = fmaxf(mrun[r], rmax[r]);
            alpha[r] = ex2(mrun[r] - mn);
            mrun[r] = mn;
        }
        float lsum[2] = {0.f, 0.f};
#pragma unroll
        for (int nt = 0; nt < 8; nt++)
#pragma unroll
            for (int e = 0; e < 4; e++) {
                const float p = ex2(S[nt][e] - mrun[e >> 1]);
                S[nt][e] = p;
                lsum[e >> 1] += p;
            }
#pragma unroll
        for (int r = 0; r < 2; r++) {
            lsum[r] += __shfl_xor_sync(0xffffffffu, lsum[r], 1);
            lsum[r] += __shfl_xor_sync(0xffffffffu, lsum[r], 2);
            lrun[r] = lrun[r] * alpha[r] + lsum[r];
        }
#pragma unroll
        for (int nt = 0; nt < 8; nt++)
#pragma unroll
            for (int e = 0; e < 4; e++) O[nt][e] *= alpha[e >> 1];

        // ---- PV: O += Ph*Vh + Ph*Vl + Pl*Vh ----
#pragma unroll
        for (int kt = 0; kt < 4; kt++) {
            uint32_t ph[4], pl[4];
            {
                const float* sp0 = S[2 * kt];
                const float* sp1 = S[2 * kt + 1];
#pragma unroll
                for (int h2 = 0; h2 < 2; h2++) {
                    const float* sp = h2 ? sp1 : sp0;
#pragma unroll
                    for (int pp = 0; pp < 2; pp++) {
                        const float f0 = sp[2 * pp], f1 = sp[2 * pp + 1];
                        const uint32_t u0 = __float_as_uint(f0);
                        const uint32_t u1 = __float_as_uint(f1);
                        ph[2 * h2 + pp] = prmt_hi2(u0, u1);
                        const float l0 = f0 - __uint_as_float(u0 & 0xFFFF0000u);
                        const float l1 = f1 - __uint_as_float(u1 & 0xFFFF0000u);
                        pl[2 * h2 + pp] = prmt_hi2(__float_as_uint(l0),
                                                   __float_as_uint(l1));
                    }
                }
            }
#pragma unroll
            for (int hp = 0; hp < 4; hp++) {
                uint32_t vh4[4], vl4[4];
                ldsm4t(smem_u32(&sm[vbase + (kt * 16 + v_row) * VPITCH + hp * 16 + v_col]), vh4);
                ldsm4t(smem_u32(&sm[vbase + PLSTRIDE + (kt * 16 + v_row) * VPITCH + hp * 16 + v_col]), vl4);
                mma16816(O[2 * hp],     ph, vh4[0], vh4[1]);
                mma16816(O[2 * hp + 1], ph, vh4[2], vh4[3]);
                mma16816(O[2 * hp],     ph, vl4[0], vl4[1]);
                mma16816(O[2 * hp + 1], ph, vl4[2], vl4[3]);
                mma16816(O[2 * hp],     pl, vh4[0], vh4[1]);
                mma16816(O[2 * hp + 1], pl, vh4[2], vh4[3]);
            }
        }
    }

    // ---- epilogue: normalize, split, write g_sas [hi | hi | lo] ----
    const int b = bh / NHEAD;
    const int h = bh % NHEAD;
#pragma unroll
    for (int r = 0; r < 2; r++) {
        const float inv = 1.f / lrun[r];
        const int n = q0 + wid * 16 + (lane >> 2) + r * 8;
        __nv_bfloat16* rowp = g_sas + (size_t)(b * SEQ + n) * K2;
#pragma unroll
        for (int nt = 0; nt < 8; nt++) {
            const int c = h * HDIM + nt * 8 + ((lane & 3) << 1);
            const float f0 = O[nt][2 * r + 0] * inv;
            const float f1 = O[nt][2 * r + 1] * inv;
            __nv_bfloat16 h0 = __float2bfloat16(f0), h1 = __float2bfloat16(f1);
            __nv_bfloat162 hv; hv.x = h0; hv.y = h1;
            __nv_bfloat162 lv;
            lv.x = __float2bfloat16(f0 - __bfloat162float(h0));
            lv.y = __float2bfloat16(f1 - __bfloat162float(h1));
            *(__nv_bfloat162*)&rowp[c]        = hv;
            *(__nv_bfloat162*)&rowp[768 + c]  = hv;
            *(__nv_bfloat162*)&rowp[1536 + c] = lv;
        }
    }
}

// ---------------------------------------------------------------------------
extern "C" void kernel_launch(void* const* d_in, const int* in_sizes, int n_in,
                              void* d_out, int out_size)
{
    const float* x      = (const float*)d_in[0];  // [B, N, D]
    const float* W_kqv  = (const float*)d_in[1];  // [H, 3*HD, D]
    const float* b_kqv  = (const float*)d_in[2];  // [H, 3*HD]
    const float* W_proj = (const float*)d_in[3];  // [D, D]
    const float* b_proj = (const float*)d_in[4];  // [D]
    float* out = (float*)d_out;

    (void)in_sizes; (void)n_in; (void)out_size;

    cudaFuncSetAttribute(attn_tc, cudaFuncAttributeMaxDynamicSharedMemorySize,
                         ATTN_SMEM_BYTES);
    cudaFuncSetAttribute(gemm_qkv_tc, cudaFuncAttributeMaxDynamicSharedMemorySize,
                         GEMM_SMEM_BYTES);
    cudaFuncSetAttribute(gemm_proj_seg, cudaFuncAttributeMaxDynamicSharedMemorySize,
                         GEMM_SMEM_BYTES);

    // fused split conversions (X, Wkqv, Wproj)
    convert_all<<<5376, 256>>>(x, W_kqv, W_proj);

    // QKV projection (HMMA, K-chunk 64, 3-stage) + bf16 hi/lo split epilogue
    {
        dim3 grid(QKV_COLS / 128, M_ROWS / 128);   // 18 x 32
        gemm_qkv_tc<<<grid, 256, GEMM_SMEM_BYTES>>>(b_kqv);
    }
    // tensor-core causal flash attention (64-row q-tiles), writes g_sas
    {
        dim3 grid(SEQ / 64, BATCH * NHEAD);        // 32 x 24
        attn_tc<<<grid, 128, ATTN_SMEM_BYTES>>>();
    }
    // output projection: split-K x3 + deterministic reduce
    {
        dim3 grid(DMODEL / 128, M_ROWS / 128, 3);  // 6 x 32 x 3
        gemm_proj_seg<<<grid, 256, GEMM_SMEM_BYTES>>>();
        proj_reduce<<<3072, 256>>>(b_proj, out);
    }
}